// round 1
// baseline (speedup 1.0000x reference)
#include <cuda_runtime.h>
#include <math.h>

#define NH     12
#define DH     64
#define DM     768
#define NB     256
#define LEN    1024
#define BATCH  8

// ---------------- device scratch (static; no allocations) ----------------
__device__ float g_Bmat[BATCH * NB * DM];         //  6.3 MB
__device__ float g_Kmat[BATCH * NB * DM];         //  6.3 MB
__device__ float g_Vmat[BATCH * NB * DM];         //  6.3 MB
__device__ float g_Qmat[BATCH * LEN * DM];        // 25.2 MB
__device__ float g_scores[BATCH * NH * LEN * NB]; // 100.7 MB
__device__ float g_mu[BATCH * NH * LEN];
__device__ float g_ss[BATCH * NH * LEN];
__device__ float g_ctx[BATCH * LEN * DM];         // 25.2 MB

// ---------------- generic strided batched fp32 GEMM ----------------
// C[m,n] = alpha * sum_k A[m,k] * B[k,n], arbitrary strides, 2 batch dims.
// Tiles: 128x128x16, 256 threads, 8x8 micro (2x2 blocks of 4x4 via float4).
#define BM 128
#define BN 128
#define BK 16
#define LDT 132   // padded row (floats); 132*4B is 16B-aligned per row

__global__ __launch_bounds__(256)
void gemm_kernel(int M, int N, int K,
                 const float* __restrict__ A, long long sAm, long long sAk,
                 long long sAb1, long long sAb2,
                 const float* __restrict__ B, long long sBk, long long sBn,
                 long long sBb1, long long sBb2,
                 float* __restrict__ C, long long sCm, long long sCn,
                 long long sCb1, long long sCb2,
                 int nz2, float alpha)
{
    __shared__ __align__(16) float As[BK][LDT];
    __shared__ __align__(16) float Bs[BK][LDT];

    int z  = blockIdx.z;
    int z1 = z / nz2;
    int z2 = z - z1 * nz2;
    A += z1 * sAb1 + z2 * sAb2;
    B += z1 * sBb1 + z2 * sBb2;
    C += z1 * sCb1 + z2 * sCb2;

    const int m0 = blockIdx.y * BM;
    const int n0 = blockIdx.x * BN;
    const int tid = threadIdx.x;
    const int ty = tid >> 4;   // 0..15
    const int tx = tid & 15;   // 0..15

    const bool aKfast = (sAk == 1);
    const bool bKfast = (sBk == 1);

    float acc[8][8];
#pragma unroll
    for (int i = 0; i < 8; i++)
#pragma unroll
        for (int j = 0; j < 8; j++) acc[i][j] = 0.f;

    for (int k0 = 0; k0 < K; k0 += BK) {
        // ---- load A tile ----
        if (aKfast) {
#pragma unroll
            for (int i = 0; i < 8; i++) {
                int idx = tid + i * 256;
                int kk = idx & 15, mm = idx >> 4;
                As[kk][mm] = A[(long long)(m0 + mm) * sAm + (k0 + kk)];
            }
        } else {
#pragma unroll
            for (int i = 0; i < 8; i++) {
                int idx = tid + i * 256;
                int mm = idx & 127, kk = idx >> 7;
                As[kk][mm] = A[(long long)(m0 + mm) * sAm + (long long)(k0 + kk) * sAk];
            }
        }
        // ---- load B tile ----
        if (bKfast) {
#pragma unroll
            for (int i = 0; i < 8; i++) {
                int idx = tid + i * 256;
                int kk = idx & 15, nn = idx >> 4;
                Bs[kk][nn] = B[(long long)(n0 + nn) * sBn + (k0 + kk)];
            }
        } else {
#pragma unroll
            for (int i = 0; i < 8; i++) {
                int idx = tid + i * 256;
                int nn = idx & 127, kk = idx >> 7;
                Bs[kk][nn] = B[(long long)(k0 + kk) * sBk + (long long)(n0 + nn) * sBn];
            }
        }
        __syncthreads();

#pragma unroll
        for (int kk = 0; kk < BK; kk++) {
            float4 a0 = *(const float4*)&As[kk][ty * 4];
            float4 a1 = *(const float4*)&As[kk][64 + ty * 4];
            float4 b0 = *(const float4*)&Bs[kk][tx * 4];
            float4 b1 = *(const float4*)&Bs[kk][64 + tx * 4];
            float a[8] = {a0.x, a0.y, a0.z, a0.w, a1.x, a1.y, a1.z, a1.w};
            float b[8] = {b0.x, b0.y, b0.z, b0.w, b1.x, b1.y, b1.z, b1.w};
#pragma unroll
            for (int i = 0; i < 8; i++)
#pragma unroll
                for (int j = 0; j < 8; j++) acc[i][j] += a[i] * b[j];
        }
        __syncthreads();
    }

#pragma unroll
    for (int i = 0; i < 8; i++) {
        int m = m0 + ((i < 4) ? (ty * 4 + i) : (64 + ty * 4 + i - 4));
#pragma unroll
        for (int j = 0; j < 8; j++) {
            int n = n0 + ((j < 4) ? (tx * 4 + j) : (64 + tx * 4 + j - 4));
            C[(long long)m * sCm + (long long)n * sCn] = alpha * acc[i][j];
        }
    }
}

// ---------------- mu / sigma^2: warp-per-row dot with w_mu / w_sigma ----------------
__global__ __launch_bounds__(256)
void musig_kernel(const float* __restrict__ scores,
                  const float* __restrict__ w_mu,
                  const float* __restrict__ w_sigma,
                  float* __restrict__ mu_out, float* __restrict__ ss_out)
{
    __shared__ float wm[NB], ws[NB];
    int tid = threadIdx.x;
    if (tid < NB) { wm[tid] = w_mu[tid]; ws[tid] = w_sigma[tid]; }
    __syncthreads();

    int warp = tid >> 5, lane = tid & 31;
    int row = blockIdx.x * 8 + warp;   // < BATCH*NH*LEN = 98304
    const float* srow = scores + (long long)row * NB;

    float dm = 0.f, dsg = 0.f;
#pragma unroll
    for (int i = 0; i < 8; i++) {
        float v = srow[i * 32 + lane];
        dm  += v * wm[i * 32 + lane];
        dsg += v * ws[i * 32 + lane];
    }
#pragma unroll
    for (int o = 16; o; o >>= 1) {
        dm  += __shfl_xor_sync(0xffffffffu, dm, o);
        dsg += __shfl_xor_sync(0xffffffffu, dsg, o);
    }
    if (lane == 0) {
        mu_out[row] = 1.f / (1.f + __expf(-dm));
        ss_out[row] = (dsg > 20.f) ? dsg : log1pf(__expf(dsg));
    }
}

// ---------------- fused r-compute + ctx = r @ V ----------------
// r[m,n] = c * inv_s * exp(-0.5*((mu_m - mu_b[n])*inv_s)^2),
// inv_s = rsqrt(sigma_b[n]^2 + sigma_sq_m); sigma_b alternates with period 2,
// so only 2 rsqrts per query row. r staged in smem, never hits HBM.
__global__ __launch_bounds__(256)
void rv_kernel(const float* __restrict__ mu,
               const float* __restrict__ ss,
               const float* __restrict__ mu_b,
               const float* __restrict__ sigma_b,
               const float* __restrict__ V,
               float* __restrict__ ctx)
{
    __shared__ __align__(16) float Vs[64][68];
    __shared__ float rs[64][68];
    __shared__ float mub[NB];
    __shared__ float invs[64][2];
    __shared__ float mus[64];

    const int tid = threadIdx.x;
    const int bh = blockIdx.y;
    const int b = bh / NH, h = bh - b * NH;
    const int m0 = blockIdx.x * 64;
    const int rowbase = bh * LEN + m0;

    if (tid < NB) mub[tid] = mu_b[tid];
    if (tid < 64) mus[tid] = mu[rowbase + tid];
    if (tid < 128) {
        int row = tid >> 1, p = tid & 1;
        float sb = sigma_b[p];
        invs[row][p] = rsqrtf(sb * sb + ss[rowbase + row]);
    }
    __syncthreads();

    const int ty = tid >> 4, tx = tid & 15;   // m micro = ty*4.., d micro = tx*4..
    float acc[4][4];
#pragma unroll
    for (int i = 0; i < 4; i++)
#pragma unroll
        for (int j = 0; j < 4; j++) acc[i][j] = 0.f;

    const float* Vbh = V + (long long)b * NB * DM + h * DH;
    const float C_PHI = 0.3989422804014327f;

    for (int nc = 0; nc < 4; nc++) {
        __syncthreads();
        // load V chunk [64 n][64 d]
#pragma unroll
        for (int i = 0; i < 16; i++) {
            int idx = tid + i * 256;
            int k = idx >> 6, d = idx & 63;
            Vs[k][d] = Vbh[(long long)(nc * 64 + k) * DM + d];
        }
        // compute r chunk [64 m][64 n]
#pragma unroll
        for (int i = 0; i < 16; i++) {
            int idx = tid + i * 256;
            int n = idx & 63, m = idx >> 6;
            float iv = invs[m][n & 1];
            float t = (mus[m] - mub[nc * 64 + n]) * iv;
            rs[m][n] = C_PHI * iv * __expf(-0.5f * t * t);
        }
        __syncthreads();
        // acc += r_chunk @ V_chunk
#pragma unroll 16
        for (int k = 0; k < 64; k++) {
            float a0 = rs[ty * 4 + 0][k];
            float a1 = rs[ty * 4 + 1][k];
            float a2 = rs[ty * 4 + 2][k];
            float a3 = rs[ty * 4 + 3][k];
            float4 bv = *(const float4*)&Vs[k][tx * 4];
            acc[0][0] += a0 * bv.x; acc[0][1] += a0 * bv.y; acc[0][2] += a0 * bv.z; acc[0][3] += a0 * bv.w;
            acc[1][0] += a1 * bv.x; acc[1][1] += a1 * bv.y; acc[1][2] += a1 * bv.z; acc[1][3] += a1 * bv.w;
            acc[2][0] += a2 * bv.x; acc[2][1] += a2 * bv.y; acc[2][2] += a2 * bv.z; acc[2][3] += a2 * bv.w;
            acc[3][0] += a3 * bv.x; acc[3][1] += a3 * bv.y; acc[3][2] += a3 * bv.z; acc[3][3] += a3 * bv.w;
        }
    }

    float* cbase = ctx + (long long)b * LEN * DM + (long long)m0 * DM + h * DH;
#pragma unroll
    for (int i = 0; i < 4; i++)
#pragma unroll
        for (int j = 0; j < 4; j++)
            cbase[(long long)(ty * 4 + i) * DM + tx * 4 + j] = acc[i][j];
}

// ---------------- launch ----------------
extern "C" void kernel_launch(void* const* d_in, const int* in_sizes, int n_in,
                              void* d_out, int out_size)
{
    const float* x       = (const float*)d_in[0];
    const float* q       = (const float*)d_in[1];
    const float* Wq      = (const float*)d_in[2];
    const float* Wk      = (const float*)d_in[3];
    const float* Wv      = (const float*)d_in[4];
    const float* Wo      = (const float*)d_in[5];
    const float* w_mu    = (const float*)d_in[6];
    const float* w_sigma = (const float*)d_in[7];
    const float* mu_b    = (const float*)d_in[8];
    const float* sigma_b = (const float*)d_in[9];
    const float* G       = (const float*)d_in[10];
    float* out = (float*)d_out;

    void *pB, *pK, *pV, *pQ, *pS, *pMu, *pSs, *pCtx;
    cudaGetSymbolAddress(&pB,  g_Bmat);
    cudaGetSymbolAddress(&pK,  g_Kmat);
    cudaGetSymbolAddress(&pV,  g_Vmat);
    cudaGetSymbolAddress(&pQ,  g_Qmat);
    cudaGetSymbolAddress(&pS,  g_scores);
    cudaGetSymbolAddress(&pMu, g_mu);
    cudaGetSymbolAddress(&pSs, g_ss);
    cudaGetSymbolAddress(&pCtx, g_ctx);

    dim3 blk(256);
    const long long BD = (long long)BATCH * DM;     // 6144
    const long long NBDM = (long long)NB * DM;      // 196608
    const long long LDM = (long long)LEN * DM;      // 786432

    // 1. Bmat[b] (256x768) = G^T (256x1024) @ x_b (1024x768)
    gemm_kernel<<<dim3(DM / BN, NB / BM, BATCH), blk>>>(
        NB, DM, LEN,
        G,  1, NB, 0, 0,
        x,  BD, 1, DM, 0,
        (float*)pB, DM, 1, NBDM, 0,
        1, 1.0f);

    // 2. K[b] = Bmat_b @ Wk^T
    gemm_kernel<<<dim3(DM / BN, NB / BM, BATCH), blk>>>(
        NB, DM, DM,
        (const float*)pB, DM, 1, NBDM, 0,
        Wk, 1, DM, 0, 0,
        (float*)pK, DM, 1, NBDM, 0,
        1, 1.0f);

    // 3. V[b] = Bmat_b @ Wv^T
    gemm_kernel<<<dim3(DM / BN, NB / BM, BATCH), blk>>>(
        NB, DM, DM,
        (const float*)pB, DM, 1, NBDM, 0,
        Wv, 1, DM, 0, 0,
        (float*)pV, DM, 1, NBDM, 0,
        1, 1.0f);

    // 4. Q[b] = q_b @ Wq^T
    gemm_kernel<<<dim3(DM / BN, LEN / BM, BATCH), blk>>>(
        LEN, DM, DM,
        q,  BD, 1, DM, 0,
        Wq, 1, DM, 0, 0,
        (float*)pQ, DM, 1, LDM, 0,
        1, 1.0f);

    // 5. scores[b,h] = Q_bh (1024x64) @ K_bh^T (64x256) / 8
    gemm_kernel<<<dim3(NB / BN, LEN / BM, BATCH * NH), blk>>>(
        LEN, NB, DH,
        (const float*)pQ, DM, 1, LDM, DH,
        (const float*)pK, 1, DM, NBDM, DH,
        (float*)pS, NB, 1, (long long)NH * LEN * NB, (long long)LEN * NB,
        NH, 0.125f);

    // 6. mu / sigma_sq
    musig_kernel<<<(BATCH * NH * LEN) / 8, blk>>>(
        (const float*)pS, w_mu, w_sigma, (float*)pMu, (float*)pSs);

    // 7. fused r + ctx = r @ V
    rv_kernel<<<dim3(LEN / 64, BATCH * NH), blk>>>(
        (const float*)pMu, (const float*)pSs, mu_b, sigma_b,
        (const float*)pV, (float*)pCtx);

    // 8. out[b] = ctx_b @ Wo^T
    gemm_kernel<<<dim3(DM / BN, LEN / BM, BATCH), blk>>>(
        LEN, DM, DM,
        (const float*)pCtx, DM, 1, LDM, 0,
        Wo, 1, DM, 0, 0,
        out, DM, 1, LDM, 0,
        1, 1.0f);
}

// round 2
// speedup vs baseline: 2.2271x; 2.2271x over previous
#include <cuda_runtime.h>
#include <cuda_bf16.h>
#include <math.h>
#include <stdint.h>

#define NH     12
#define DH     64
#define DM     768
#define NB     256
#define LEN    1024
#define BATCH  8

typedef __nv_bfloat16 bf16;

// ---------------- device scratch (static; no allocations) ----------------
__device__ __align__(16) bf16 g_q0 [BATCH * LEN * DM];
__device__ __align__(16) bf16 g_q1 [BATCH * LEN * DM];
__device__ __align__(16) bf16 g_xt0[BATCH * DM * LEN];   // x transposed: [b][d][l]
__device__ __align__(16) bf16 g_xt1[BATCH * DM * LEN];
__device__ __align__(16) bf16 g_Gt0[NB * LEN];           // G transposed: [n][l]
__device__ __align__(16) bf16 g_Gt1[NB * LEN];
__device__ __align__(16) bf16 g_Wq0[DM * DM]; __device__ __align__(16) bf16 g_Wq1[DM * DM];
__device__ __align__(16) bf16 g_Wk0[DM * DM]; __device__ __align__(16) bf16 g_Wk1[DM * DM];
__device__ __align__(16) bf16 g_Wv0[DM * DM]; __device__ __align__(16) bf16 g_Wv1[DM * DM];
__device__ __align__(16) bf16 g_Wo0[DM * DM]; __device__ __align__(16) bf16 g_Wo1[DM * DM];
__device__ __align__(16) bf16 g_B0 [BATCH * NB * DM];
__device__ __align__(16) bf16 g_B1 [BATCH * NB * DM];
__device__ __align__(16) bf16 g_K0 [BATCH * NB * DM];
__device__ __align__(16) bf16 g_K1 [BATCH * NB * DM];
__device__ float g_V[BATCH * NB * DM];
__device__ __align__(16) bf16 g_Q0 [BATCH * LEN * DM];
__device__ __align__(16) bf16 g_Q1 [BATCH * LEN * DM];
__device__ float g_scores[BATCH * NH * LEN * NB];
__device__ float g_mu[BATCH * NH * LEN];
__device__ float g_ss[BATCH * NH * LEN];
__device__ __align__(16) bf16 g_ctx0[BATCH * LEN * DM];
__device__ __align__(16) bf16 g_ctx1[BATCH * LEN * DM];

// ---------------- split conversion: fp32 -> (hi, lo) bf16 ----------------
__global__ __launch_bounds__(256)
void split_kernel(const float* __restrict__ src, bf16* __restrict__ d0,
                  bf16* __restrict__ d1, int n)
{
    int i = (blockIdx.x * 256 + threadIdx.x) * 4;
    if (i >= n) return;
    float4 v = *(const float4*)(src + i);
    bf16 h0 = __float2bfloat16(v.x), h1 = __float2bfloat16(v.y);
    bf16 h2 = __float2bfloat16(v.z), h3 = __float2bfloat16(v.w);
    bf16 l0 = __float2bfloat16(v.x - __bfloat162float(h0));
    bf16 l1 = __float2bfloat16(v.y - __bfloat162float(h1));
    bf16 l2 = __float2bfloat16(v.z - __bfloat162float(h2));
    bf16 l3 = __float2bfloat16(v.w - __bfloat162float(h3));
    *(__nv_bfloat162*)(d0 + i)     = __nv_bfloat162(h0, h1);
    *(__nv_bfloat162*)(d0 + i + 2) = __nv_bfloat162(h2, h3);
    *(__nv_bfloat162*)(d1 + i)     = __nv_bfloat162(l0, l1);
    *(__nv_bfloat162*)(d1 + i + 2) = __nv_bfloat162(l2, l3);
}

// ---------------- transpose + split: out[n][m] = in[m][n] ----------------
__global__ __launch_bounds__(256)
void tsplit_kernel(const float* __restrict__ src, long long sb_in, int ldin,
                   bf16* __restrict__ d0, bf16* __restrict__ d1,
                   long long sb_out, int ldout)
{
    __shared__ float tile[32][33];
    int b = blockIdx.z;
    const float* s = src + (long long)b * sb_in;
    int m0 = blockIdx.y * 32, n0 = blockIdx.x * 32;
#pragma unroll
    for (int i = 0; i < 4; i++) {
        int m = m0 + threadIdx.y + i * 8;
        tile[threadIdx.y + i * 8][threadIdx.x] = s[(long long)m * ldin + n0 + threadIdx.x];
    }
    __syncthreads();
#pragma unroll
    for (int i = 0; i < 4; i++) {
        int n = n0 + threadIdx.y + i * 8;
        float v = tile[threadIdx.x][threadIdx.y + i * 8];
        long long o = (long long)b * sb_out + (long long)n * ldout + m0 + threadIdx.x;
        bf16 h = __float2bfloat16(v);
        d0[o] = h;
        d1[o] = __float2bfloat16(v - __bfloat162float(h));
    }
}

// ---------------- mma helpers ----------------
__device__ __forceinline__ void mma16816(float* c, const uint32_t* a, const uint32_t* b)
{
    asm volatile("mma.sync.aligned.m16n8k16.row.col.f32.bf16.bf16.f32 "
                 "{%0,%1,%2,%3}, {%4,%5,%6,%7}, {%8,%9}, {%0,%1,%2,%3};"
                 : "+f"(c[0]), "+f"(c[1]), "+f"(c[2]), "+f"(c[3])
                 : "r"(a[0]), "r"(a[1]), "r"(a[2]), "r"(a[3]), "r"(b[0]), "r"(b[1]));
}
__device__ __forceinline__ void ldsm4(uint32_t* r, const bf16* p)
{
    uint32_t a = (uint32_t)__cvta_generic_to_shared(p);
    asm volatile("ldmatrix.sync.aligned.m8n8.x4.shared.b16 {%0,%1,%2,%3}, [%4];"
                 : "=r"(r[0]), "=r"(r[1]), "=r"(r[2]), "=r"(r[3]) : "r"(a));
}
__device__ __forceinline__ void ldsm2(uint32_t* r, const bf16* p)
{
    uint32_t a = (uint32_t)__cvta_generic_to_shared(p);
    asm volatile("ldmatrix.sync.aligned.m8n8.x2.shared.b16 {%0,%1}, [%2];"
                 : "=r"(r[0]), "=r"(r[1]) : "r"(a));
}
__device__ __forceinline__ void cpa16(bf16* s, const bf16* g)
{
    uint32_t sa = (uint32_t)__cvta_generic_to_shared(s);
    asm volatile("cp.async.cg.shared.global [%0], [%1], 16;" :: "r"(sa), "l"(g));
}

// ---------------- split-bf16 tensor-core GEMM ----------------
// C[m][n] = alpha * sum_k A[m][k]*B[n][k] with A ~ A0+A1, B ~ B0+B1 bf16,
// computed as A0B0 + A0B1 + A1B0 (fp32 accumulate). All dims are multiples
// of the tile (M%128==0, N%128==0, K%32==0) for this problem.
#define LDS_ROW 40                    // 32 halves + 8 pad
#define TSZ     (128 * LDS_ROW)       // one tile, in halves
#define STAGE_H (4 * TSZ)             // 4 tiles per stage
#define GSMEM_BYTES (2 * STAGE_H * 2) // 81920 bytes

__global__ __launch_bounds__(256)
void mma_gemm(int K,
              const bf16* __restrict__ A0, const bf16* __restrict__ A1,
              long long lda, long long sAb1, long long sAb2,
              const bf16* __restrict__ B0, const bf16* __restrict__ B1,
              long long ldb, long long sBb1, long long sBb2,
              float* __restrict__ C, bf16* __restrict__ C0, bf16* __restrict__ C1,
              long long ldc, long long sCb1, long long sCb2,
              int nz2, float alpha, int mode)
{
    extern __shared__ bf16 sm[];

    int z = blockIdx.z, z1 = z / nz2, z2 = z - z1 * nz2;
    A0 += z1 * sAb1 + z2 * sAb2;  A1 += z1 * sAb1 + z2 * sAb2;
    B0 += z1 * sBb1 + z2 * sBb2;  B1 += z1 * sBb1 + z2 * sBb2;
    const long long coff = z1 * sCb1 + z2 * sCb2;

    const int m0 = blockIdx.y * 128, n0 = blockIdx.x * 128;
    const int tid = threadIdx.x, lane = tid & 31, wid = tid >> 5;
    const int wm = (wid >> 2) * 64, wn = (wid & 3) * 32;

    float acc[4][4][4];
#pragma unroll
    for (int mt = 0; mt < 4; mt++)
#pragma unroll
        for (int nt = 0; nt < 4; nt++)
#pragma unroll
            for (int i = 0; i < 4; i++) acc[mt][nt][i] = 0.f;

    const int nstages = K >> 5;   // K/32

    // ---- async stage loader ----
    const int lrow = tid >> 2, lseg = tid & 3;
    auto load_stage = [&](int st, int k0) {
        bf16* base = sm + st * STAGE_H;
#pragma unroll
        for (int it = 0; it < 2; it++) {
            int row = lrow + it * 64;
            int so = row * LDS_ROW + lseg * 8;
            long long goA = (long long)(m0 + row) * lda + k0 + lseg * 8;
            long long goB = (long long)(n0 + row) * ldb + k0 + lseg * 8;
            cpa16(base + so,           A0 + goA);
            cpa16(base + TSZ + so,     A1 + goA);
            cpa16(base + 2 * TSZ + so, B0 + goB);
            cpa16(base + 3 * TSZ + so, B1 + goB);
        }
        asm volatile("cp.async.commit_group;");
    };

    load_stage(0, 0);

    for (int s = 0; s < nstages; s++) {
        if (s + 1 < nstages) {
            load_stage((s + 1) & 1, (s + 1) << 5);
            asm volatile("cp.async.wait_group 1;");
        } else {
            asm volatile("cp.async.wait_group 0;");
        }
        __syncthreads();

        const bf16* As0 = sm + (s & 1) * STAGE_H;
        const bf16* As1 = As0 + TSZ;
        const bf16* Bs0 = As0 + 2 * TSZ;
        const bf16* Bs1 = As0 + 3 * TSZ;

#pragma unroll
        for (int kk = 0; kk < 2; kk++) {
            const int ar = lane & 15, ac = kk * 16 + (lane >> 4) * 8;
            const int br = lane & 7,  bc = kk * 16 + ((lane >> 3) & 1) * 8;
            uint32_t af[4][4], bf0[4][2], bf1[4][2];
#pragma unroll
            for (int mt = 0; mt < 4; mt++)
                ldsm4(af[mt], As0 + (wm + mt * 16 + ar) * LDS_ROW + ac);
#pragma unroll
            for (int nt = 0; nt < 4; nt++) {
                ldsm2(bf0[nt], Bs0 + (wn + nt * 8 + br) * LDS_ROW + bc);
                ldsm2(bf1[nt], Bs1 + (wn + nt * 8 + br) * LDS_ROW + bc);
            }
#pragma unroll
            for (int mt = 0; mt < 4; mt++)
#pragma unroll
                for (int nt = 0; nt < 4; nt++) mma16816(acc[mt][nt], af[mt], bf0[nt]);
#pragma unroll
            for (int mt = 0; mt < 4; mt++)
#pragma unroll
                for (int nt = 0; nt < 4; nt++) mma16816(acc[mt][nt], af[mt], bf1[nt]);
#pragma unroll
            for (int mt = 0; mt < 4; mt++)
                ldsm4(af[mt], As1 + (wm + mt * 16 + ar) * LDS_ROW + ac);
#pragma unroll
            for (int mt = 0; mt < 4; mt++)
#pragma unroll
                for (int nt = 0; nt < 4; nt++) mma16816(acc[mt][nt], af[mt], bf0[nt]);
        }
        __syncthreads();
    }

    // ---- epilogue ----
    const int g = lane >> 2, c2 = (lane & 3) * 2;
#pragma unroll
    for (int mt = 0; mt < 4; mt++) {
#pragma unroll
        for (int nt = 0; nt < 4; nt++) {
            int row = m0 + wm + mt * 16 + g;
            int col = n0 + wn + nt * 8 + c2;
            float v0 = alpha * acc[mt][nt][0], v1 = alpha * acc[mt][nt][1];
            float v2 = alpha * acc[mt][nt][2], v3 = alpha * acc[mt][nt][3];
            if (mode == 0) {
                *(float2*)&C[coff + (long long)row * ldc + col]       = make_float2(v0, v1);
                *(float2*)&C[coff + (long long)(row + 8) * ldc + col] = make_float2(v2, v3);
            } else {
                bf16 h0 = __float2bfloat16(v0), h1 = __float2bfloat16(v1);
                bf16 h2 = __float2bfloat16(v2), h3 = __float2bfloat16(v3);
                bf16 l0 = __float2bfloat16(v0 - __bfloat162float(h0));
                bf16 l1 = __float2bfloat16(v1 - __bfloat162float(h1));
                bf16 l2 = __float2bfloat16(v2 - __bfloat162float(h2));
                bf16 l3 = __float2bfloat16(v3 - __bfloat162float(h3));
                long long o0 = coff + (long long)row * ldc + col;
                long long o1 = coff + (long long)(row + 8) * ldc + col;
                *(__nv_bfloat162*)(C0 + o0) = __nv_bfloat162(h0, h1);
                *(__nv_bfloat162*)(C0 + o1) = __nv_bfloat162(h2, h3);
                *(__nv_bfloat162*)(C1 + o0) = __nv_bfloat162(l0, l1);
                *(__nv_bfloat162*)(C1 + o1) = __nv_bfloat162(l2, l3);
            }
        }
    }
}

// ---------------- mu / sigma^2 ----------------
__global__ __launch_bounds__(256)
void musig_kernel(const float* __restrict__ scores,
                  const float* __restrict__ w_mu,
                  const float* __restrict__ w_sigma,
                  float* __restrict__ mu_out, float* __restrict__ ss_out)
{
    __shared__ float wm[NB], ws[NB];
    int tid = threadIdx.x;
    if (tid < NB) { wm[tid] = w_mu[tid]; ws[tid] = w_sigma[tid]; }
    __syncthreads();

    int warp = tid >> 5, lane = tid & 31;
    int row = blockIdx.x * 8 + warp;
    const float* srow = scores + (long long)row * NB;

    float dm = 0.f, dsg = 0.f;
#pragma unroll
    for (int i = 0; i < 8; i++) {
        float v = srow[i * 32 + lane];
        dm  += v * wm[i * 32 + lane];
        dsg += v * ws[i * 32 + lane];
    }
#pragma unroll
    for (int o = 16; o; o >>= 1) {
        dm  += __shfl_xor_sync(0xffffffffu, dm, o);
        dsg += __shfl_xor_sync(0xffffffffu, dsg, o);
    }
    if (lane == 0) {
        mu_out[row] = 1.f / (1.f + __expf(-dm));
        ss_out[row] = (dsg > 20.f) ? dsg : log1pf(__expf(dsg));
    }
}

// ---------------- fused r-compute + ctx = r @ V (writes split ctx) ----------------
__global__ __launch_bounds__(256)
void rv_kernel(const float* __restrict__ mu,
               const float* __restrict__ ss,
               const float* __restrict__ mu_b,
               const float* __restrict__ sigma_b,
               const float* __restrict__ V,
               bf16* __restrict__ ctx0, bf16* __restrict__ ctx1)
{
    __shared__ __align__(16) float Vs[64][68];
    __shared__ float rs[64][68];
    __shared__ float mub[NB];
    __shared__ float invs[64][2];
    __shared__ float mus[64];

    const int tid = threadIdx.x;
    const int bh = blockIdx.y;
    const int b = bh / NH, h = bh - b * NH;
    const int m0 = blockIdx.x * 64;
    const int rowbase = bh * LEN + m0;

    if (tid < NB) mub[tid] = mu_b[tid];
    if (tid < 64) mus[tid] = mu[rowbase + tid];
    if (tid < 128) {
        int row = tid >> 1, p = tid & 1;
        float sb = sigma_b[p];
        invs[row][p] = rsqrtf(sb * sb + ss[rowbase + row]);
    }
    __syncthreads();

    const int ty = tid >> 4, tx = tid & 15;
    float acc[4][4];
#pragma unroll
    for (int i = 0; i < 4; i++)
#pragma unroll
        for (int j = 0; j < 4; j++) acc[i][j] = 0.f;

    const float* Vbh = V + (long long)b * NB * DM + h * DH;
    const float C_PHI = 0.3989422804014327f;

    for (int nc = 0; nc < 4; nc++) {
        __syncthreads();
#pragma unroll
        for (int i = 0; i < 16; i++) {
            int idx = tid + i * 256;
            int k = idx >> 6, d = idx & 63;
            Vs[k][d] = Vbh[(long long)(nc * 64 + k) * DM + d];
        }
#pragma unroll
        for (int i = 0; i < 16; i++) {
            int idx = tid + i * 256;
            int n = idx & 63, m = idx >> 6;
            float iv = invs[m][n & 1];
            float t = (mus[m] - mub[nc * 64 + n]) * iv;
            rs[m][n] = C_PHI * iv * __expf(-0.5f * t * t);
        }
        __syncthreads();
#pragma unroll 16
        for (int k = 0; k < 64; k++) {
            float a0 = rs[ty * 4 + 0][k];
            float a1 = rs[ty * 4 + 1][k];
            float a2 = rs[ty * 4 + 2][k];
            float a3 = rs[ty * 4 + 3][k];
            float4 bv = *(const float4*)&Vs[k][tx * 4];
            acc[0][0] += a0 * bv.x; acc[0][1] += a0 * bv.y; acc[0][2] += a0 * bv.z; acc[0][3] += a0 * bv.w;
            acc[1][0] += a1 * bv.x; acc[1][1] += a1 * bv.y; acc[1][2] += a1 * bv.z; acc[1][3] += a1 * bv.w;
            acc[2][0] += a2 * bv.x; acc[2][1] += a2 * bv.y; acc[2][2] += a2 * bv.z; acc[2][3] += a2 * bv.w;
            acc[3][0] += a3 * bv.x; acc[3][1] += a3 * bv.y; acc[3][2] += a3 * bv.z; acc[3][3] += a3 * bv.w;
        }
    }

    long long cb = (long long)b * LEN * DM + (long long)m0 * DM + h * DH;
#pragma unroll
    for (int i = 0; i < 4; i++)
#pragma unroll
        for (int j = 0; j < 4; j++) {
            long long o = cb + (long long)(ty * 4 + i) * DM + tx * 4 + j;
            float v = acc[i][j];
            bf16 hh = __float2bfloat16(v);
            ctx0[o] = hh;
            ctx1[o] = __float2bfloat16(v - __bfloat162float(hh));
        }
}

// ---------------- launch ----------------
extern "C" void kernel_launch(void* const* d_in, const int* in_sizes, int n_in,
                              void* d_out, int out_size)
{
    const float* x       = (const float*)d_in[0];
    const float* q       = (const float*)d_in[1];
    const float* Wq      = (const float*)d_in[2];
    const float* Wk      = (const float*)d_in[3];
    const float* Wv      = (const float*)d_in[4];
    const float* Wo      = (const float*)d_in[5];
    const float* w_mu    = (const float*)d_in[6];
    const float* w_sigma = (const float*)d_in[7];
    const float* mu_b    = (const float*)d_in[8];
    const float* sigma_b = (const float*)d_in[9];
    const float* G       = (const float*)d_in[10];
    float* out = (float*)d_out;

    cudaFuncSetAttribute(mma_gemm, cudaFuncAttributeMaxDynamicSharedMemorySize, GSMEM_BYTES);

    void *pq0, *pq1, *pxt0, *pxt1, *pGt0, *pGt1;
    void *pWq0, *pWq1, *pWk0, *pWk1, *pWv0, *pWv1, *pWo0, *pWo1;
    void *pB0, *pB1, *pK0, *pK1, *pV, *pQ0, *pQ1, *pS, *pMu, *pSs, *pC0, *pC1;
    cudaGetSymbolAddress(&pq0, g_q0);   cudaGetSymbolAddress(&pq1, g_q1);
    cudaGetSymbolAddress(&pxt0, g_xt0); cudaGetSymbolAddress(&pxt1, g_xt1);
    cudaGetSymbolAddress(&pGt0, g_Gt0); cudaGetSymbolAddress(&pGt1, g_Gt1);
    cudaGetSymbolAddress(&pWq0, g_Wq0); cudaGetSymbolAddress(&pWq1, g_Wq1);
    cudaGetSymbolAddress(&pWk0, g_Wk0); cudaGetSymbolAddress(&pWk1, g_Wk1);
    cudaGetSymbolAddress(&pWv0, g_Wv0); cudaGetSymbolAddress(&pWv1, g_Wv1);
    cudaGetSymbolAddress(&pWo0, g_Wo0); cudaGetSymbolAddress(&pWo1, g_Wo1);
    cudaGetSymbolAddress(&pB0, g_B0);   cudaGetSymbolAddress(&pB1, g_B1);
    cudaGetSymbolAddress(&pK0, g_K0);   cudaGetSymbolAddress(&pK1, g_K1);
    cudaGetSymbolAddress(&pV, g_V);
    cudaGetSymbolAddress(&pQ0, g_Q0);   cudaGetSymbolAddress(&pQ1, g_Q1);
    cudaGetSymbolAddress(&pS, g_scores);
    cudaGetSymbolAddress(&pMu, g_mu);   cudaGetSymbolAddress(&pSs, g_ss);
    cudaGetSymbolAddress(&pC0, g_ctx0); cudaGetSymbolAddress(&pC1, g_ctx1);

    const long long NBDM = (long long)NB * DM;     // 196608
    const long long LDM  = (long long)LEN * DM;    // 786432
    const long long DMLN = (long long)DM * LEN;    // 786432
    dim3 blk(256);

    // ---- input conversions ----
    int nW = DM * DM;
    split_kernel<<<nW / 1024, blk>>>(Wq, (bf16*)pWq0, (bf16*)pWq1, nW);
    split_kernel<<<nW / 1024, blk>>>(Wk, (bf16*)pWk0, (bf16*)pWk1, nW);
    split_kernel<<<nW / 1024, blk>>>(Wv, (bf16*)pWv0, (bf16*)pWv1, nW);
    split_kernel<<<nW / 1024, blk>>>(Wo, (bf16*)pWo0, (bf16*)pWo1, nW);
    int nq = BATCH * LEN * DM;
    split_kernel<<<nq / 1024, blk>>>(q, (bf16*)pq0, (bf16*)pq1, nq);
    tsplit_kernel<<<dim3(DM / 32, LEN / 32, BATCH), dim3(32, 8)>>>(
        x, DM, BATCH * DM, (bf16*)pxt0, (bf16*)pxt1, DMLN, LEN);
    tsplit_kernel<<<dim3(NB / 32, LEN / 32, 1), dim3(32, 8)>>>(
        G, 0, NB, (bf16*)pGt0, (bf16*)pGt1, 0, LEN);

    // ---- 1. Bmat[b] (256x768) = Gt (256x1024) . xt_b (768x1024)^T ----
    mma_gemm<<<dim3(DM / 128, NB / 128, BATCH), blk, GSMEM_BYTES>>>(
        LEN,
        (bf16*)pGt0, (bf16*)pGt1, LEN, 0, 0,
        (bf16*)pxt0, (bf16*)pxt1, LEN, DMLN, 0,
        nullptr, (bf16*)pB0, (bf16*)pB1, DM, NBDM, 0,
        1, 1.0f, 1);

    // ---- 2. K[b] = Bmat_b @ Wk^T (split out) ----
    mma_gemm<<<dim3(DM / 128, NB / 128, BATCH), blk, GSMEM_BYTES>>>(
        DM,
        (bf16*)pB0, (bf16*)pB1, DM, NBDM, 0,
        (bf16*)pWk0, (bf16*)pWk1, DM, 0, 0,
        nullptr, (bf16*)pK0, (bf16*)pK1, DM, NBDM, 0,
        1, 1.0f, 1);

    // ---- 3. V[b] = Bmat_b @ Wv^T (fp32 out) ----
    mma_gemm<<<dim3(DM / 128, NB / 128, BATCH), blk, GSMEM_BYTES>>>(
        DM,
        (bf16*)pB0, (bf16*)pB1, DM, NBDM, 0,
        (bf16*)pWv0, (bf16*)pWv1, DM, 0, 0,
        (float*)pV, nullptr, nullptr, DM, NBDM, 0,
        1, 1.0f, 0);

    // ---- 4. Q[b] = q_b @ Wq^T (split out); q rows stride BATCH*DM ----
    mma_gemm<<<dim3(DM / 128, LEN / 128, BATCH), blk, GSMEM_BYTES>>>(
        DM,
        (bf16*)pq0, (bf16*)pq1, (long long)BATCH * DM, DM, 0,
        (bf16*)pWq0, (bf16*)pWq1, DM, 0, 0,
        nullptr, (bf16*)pQ0, (bf16*)pQ1, DM, LDM, 0,
        1, 1.0f, 1);

    // ---- 5. scores[b,h] = Q_bh (1024x64) . K_bh^T / 8 (fp32 out) ----
    mma_gemm<<<dim3(NB / 128, LEN / 128, BATCH * NH), blk, GSMEM_BYTES>>>(
        DH,
        (bf16*)pQ0, (bf16*)pQ1, DM, LDM, DH,
        (bf16*)pK0, (bf16*)pK1, DM, NBDM, DH,
        (float*)pS, nullptr, nullptr, NB, (long long)NH * LEN * NB, (long long)LEN * NB,
        NH, 0.125f, 0);

    // ---- 6. mu / sigma_sq ----
    musig_kernel<<<(BATCH * NH * LEN) / 8, blk>>>(
        (const float*)pS, w_mu, w_sigma, (float*)pMu, (float*)pSs);

    // ---- 7. fused r + ctx = r @ V (split ctx out) ----
    rv_kernel<<<dim3(LEN / 64, BATCH * NH), blk>>>(
        (const float*)pMu, (const float*)pSs, mu_b, sigma_b,
        (const float*)pV, (bf16*)pC0, (bf16*)pC1);

    // ---- 8. out[b] = ctx_b @ Wo^T (fp32 out) ----
    mma_gemm<<<dim3(DM / 128, LEN / 128, BATCH), blk, GSMEM_BYTES>>>(
        DM,
        (bf16*)pC0, (bf16*)pC1, DM, LDM, 0,
        (bf16*)pWo0, (bf16*)pWo1, DM, 0, 0,
        out, nullptr, nullptr, DM, LDM, 0,
        1, 1.0f, 0);
}

// round 3
// speedup vs baseline: 2.8751x; 1.2909x over previous
#include <cuda_runtime.h>
#include <cuda_bf16.h>
#include <math.h>
#include <stdint.h>

#define NH     12
#define DH     64
#define DM     768
#define NB     256
#define LEN    1024
#define BATCH  8

typedef __nv_bfloat16 bf16;

// ---------------- device scratch (static; no allocations) ----------------
__device__ __align__(16) bf16 g_xt0[BATCH * DM * LEN];   // x transposed: [b][d][l]
__device__ __align__(16) bf16 g_xt1[BATCH * DM * LEN];
__device__ __align__(16) bf16 g_Gt0[NB * LEN];           // G transposed: [n][l]
__device__ __align__(16) bf16 g_Gt1[NB * LEN];
__device__ __align__(16) bf16 g_Wv0[DM * DM]; __device__ __align__(16) bf16 g_Wv1[DM * DM];
__device__ __align__(16) bf16 g_Wo0[DM * DM]; __device__ __align__(16) bf16 g_Wo1[DM * DM];
__device__ __align__(16) bf16 g_B0 [BATCH * NB * DM];
__device__ __align__(16) bf16 g_B1 [BATCH * NB * DM];
__device__ __align__(16) float g_Bf[BATCH * NB * DM];    // fp32 Bmat
__device__ float g_V[BATCH * NB * DM];
__device__ float g_C [BATCH * 2 * DM];    // c  = Bmat^T w      [b][s][768]
__device__ float g_KW[BATCH * 2 * DM];    // kw = Wk c          [b][s][768]
__device__ float g_T [BATCH * 24 * DM];   // t  = Wq_h^T kw     [b][h*2+s][768]
__device__ float g_mu[BATCH * NH * LEN];
__device__ float g_ss[BATCH * NH * LEN];
__device__ __align__(16) bf16 g_ctx0[BATCH * LEN * DM];
__device__ __align__(16) bf16 g_ctx1[BATCH * LEN * DM];

// ---------------- split conversion: fp32 -> (hi, lo) bf16 ----------------
__global__ __launch_bounds__(256)
void split_kernel(const float* __restrict__ src, bf16* __restrict__ d0,
                  bf16* __restrict__ d1, int n)
{
    int i = (blockIdx.x * 256 + threadIdx.x) * 4;
    if (i >= n) return;
    float4 v = *(const float4*)(src + i);
    bf16 h0 = __float2bfloat16(v.x), h1 = __float2bfloat16(v.y);
    bf16 h2 = __float2bfloat16(v.z), h3 = __float2bfloat16(v.w);
    bf16 l0 = __float2bfloat16(v.x - __bfloat162float(h0));
    bf16 l1 = __float2bfloat16(v.y - __bfloat162float(h1));
    bf16 l2 = __float2bfloat16(v.z - __bfloat162float(h2));
    bf16 l3 = __float2bfloat16(v.w - __bfloat162float(h3));
    *(__nv_bfloat162*)(d0 + i)     = __nv_bfloat162(h0, h1);
    *(__nv_bfloat162*)(d0 + i + 2) = __nv_bfloat162(h2, h3);
    *(__nv_bfloat162*)(d1 + i)     = __nv_bfloat162(l0, l1);
    *(__nv_bfloat162*)(d1 + i + 2) = __nv_bfloat162(l2, l3);
}

// ---------------- transpose + split: out[n][m] = in[m][n] ----------------
__global__ __launch_bounds__(256)
void tsplit_kernel(const float* __restrict__ src, long long sb_in, int ldin,
                   bf16* __restrict__ d0, bf16* __restrict__ d1,
                   long long sb_out, int ldout)
{
    __shared__ float tile[32][33];
    int b = blockIdx.z;
    const float* s = src + (long long)b * sb_in;
    int m0 = blockIdx.y * 32, n0 = blockIdx.x * 32;
#pragma unroll
    for (int i = 0; i < 4; i++) {
        int m = m0 + threadIdx.y + i * 8;
        tile[threadIdx.y + i * 8][threadIdx.x] = s[(long long)m * ldin + n0 + threadIdx.x];
    }
    __syncthreads();
#pragma unroll
    for (int i = 0; i < 4; i++) {
        int n = n0 + threadIdx.y + i * 8;
        float v = tile[threadIdx.x][threadIdx.y + i * 8];
        long long o = (long long)b * sb_out + (long long)n * ldout + m0 + threadIdx.x;
        bf16 h = __float2bfloat16(v);
        d0[o] = h;
        d1[o] = __float2bfloat16(v - __bfloat162float(h));
    }
}

// ---------------- mma helpers ----------------
__device__ __forceinline__ void mma16816(float* c, const uint32_t* a, const uint32_t* b)
{
    asm volatile("mma.sync.aligned.m16n8k16.row.col.f32.bf16.bf16.f32 "
                 "{%0,%1,%2,%3}, {%4,%5,%6,%7}, {%8,%9}, {%0,%1,%2,%3};"
                 : "+f"(c[0]), "+f"(c[1]), "+f"(c[2]), "+f"(c[3])
                 : "r"(a[0]), "r"(a[1]), "r"(a[2]), "r"(a[3]), "r"(b[0]), "r"(b[1]));
}
__device__ __forceinline__ void ldsm4(uint32_t* r, const bf16* p)
{
    uint32_t a = (uint32_t)__cvta_generic_to_shared(p);
    asm volatile("ldmatrix.sync.aligned.m8n8.x4.shared.b16 {%0,%1,%2,%3}, [%4];"
                 : "=r"(r[0]), "=r"(r[1]), "=r"(r[2]), "=r"(r[3]) : "r"(a));
}
__device__ __forceinline__ void ldsm2(uint32_t* r, const bf16* p)
{
    uint32_t a = (uint32_t)__cvta_generic_to_shared(p);
    asm volatile("ldmatrix.sync.aligned.m8n8.x2.shared.b16 {%0,%1}, [%2];"
                 : "=r"(r[0]), "=r"(r[1]) : "r"(a));
}
__device__ __forceinline__ void cpa16(bf16* s, const bf16* g)
{
    uint32_t sa = (uint32_t)__cvta_generic_to_shared(s);
    asm volatile("cp.async.cg.shared.global [%0], [%1], 16;" :: "r"(sa), "l"(g));
}

// ---------------- split-bf16 tensor-core GEMM ----------------
// C[m][n] = alpha * sum_k A[m][k]*B[n][k], A ~ A0+A1, B ~ B0+B1 bf16,
// computed as A0B0 + A0B1 + A1B0 (fp32 accumulate).
// mode 0: fp32 out; mode 1: split bf16 out; mode 2: fp32 AND split out.
#define LDS_ROW 40
#define TSZ     (128 * LDS_ROW)
#define STAGE_H (4 * TSZ)
#define GSMEM_BYTES (2 * STAGE_H * 2)

__global__ __launch_bounds__(256)
void mma_gemm(int K,
              const bf16* __restrict__ A0, const bf16* __restrict__ A1,
              long long lda, long long sAb1, long long sAb2,
              const bf16* __restrict__ B0, const bf16* __restrict__ B1,
              long long ldb, long long sBb1, long long sBb2,
              float* __restrict__ C, bf16* __restrict__ C0, bf16* __restrict__ C1,
              long long ldc, long long sCb1, long long sCb2,
              int nz2, float alpha, int mode)
{
    extern __shared__ bf16 sm[];

    int z = blockIdx.z, z1 = z / nz2, z2 = z - z1 * nz2;
    A0 += z1 * sAb1 + z2 * sAb2;  A1 += z1 * sAb1 + z2 * sAb2;
    B0 += z1 * sBb1 + z2 * sBb2;  B1 += z1 * sBb1 + z2 * sBb2;
    const long long coff = z1 * sCb1 + z2 * sCb2;

    const int m0 = blockIdx.y * 128, n0 = blockIdx.x * 128;
    const int tid = threadIdx.x, lane = tid & 31, wid = tid >> 5;
    const int wm = (wid >> 2) * 64, wn = (wid & 3) * 32;

    float acc[4][4][4];
#pragma unroll
    for (int mt = 0; mt < 4; mt++)
#pragma unroll
        for (int nt = 0; nt < 4; nt++)
#pragma unroll
            for (int i = 0; i < 4; i++) acc[mt][nt][i] = 0.f;

    const int nstages = K >> 5;

    const int lrow = tid >> 2, lseg = tid & 3;
    auto load_stage = [&](int st, int k0) {
        bf16* base = sm + st * STAGE_H;
#pragma unroll
        for (int it = 0; it < 2; it++) {
            int row = lrow + it * 64;
            int so = row * LDS_ROW + lseg * 8;
            long long goA = (long long)(m0 + row) * lda + k0 + lseg * 8;
            long long goB = (long long)(n0 + row) * ldb + k0 + lseg * 8;
            cpa16(base + so,           A0 + goA);
            cpa16(base + TSZ + so,     A1 + goA);
            cpa16(base + 2 * TSZ + so, B0 + goB);
            cpa16(base + 3 * TSZ + so, B1 + goB);
        }
        asm volatile("cp.async.commit_group;");
    };

    load_stage(0, 0);

    for (int s = 0; s < nstages; s++) {
        if (s + 1 < nstages) {
            load_stage((s + 1) & 1, (s + 1) << 5);
            asm volatile("cp.async.wait_group 1;");
        } else {
            asm volatile("cp.async.wait_group 0;");
        }
        __syncthreads();

        const bf16* As0 = sm + (s & 1) * STAGE_H;
        const bf16* As1 = As0 + TSZ;
        const bf16* Bs0 = As0 + 2 * TSZ;
        const bf16* Bs1 = As0 + 3 * TSZ;

#pragma unroll
        for (int kk = 0; kk < 2; kk++) {
            const int ar = lane & 15, ac = kk * 16 + (lane >> 4) * 8;
            const int br = lane & 7,  bc = kk * 16 + ((lane >> 3) & 1) * 8;
            uint32_t af[4][4], bf0[4][2], bf1[4][2];
#pragma unroll
            for (int mt = 0; mt < 4; mt++)
                ldsm4(af[mt], As0 + (wm + mt * 16 + ar) * LDS_ROW + ac);
#pragma unroll
            for (int nt = 0; nt < 4; nt++) {
                ldsm2(bf0[nt], Bs0 + (wn + nt * 8 + br) * LDS_ROW + bc);
                ldsm2(bf1[nt], Bs1 + (wn + nt * 8 + br) * LDS_ROW + bc);
            }
#pragma unroll
            for (int mt = 0; mt < 4; mt++)
#pragma unroll
                for (int nt = 0; nt < 4; nt++) mma16816(acc[mt][nt], af[mt], bf0[nt]);
#pragma unroll
            for (int mt = 0; mt < 4; mt++)
#pragma unroll
                for (int nt = 0; nt < 4; nt++) mma16816(acc[mt][nt], af[mt], bf1[nt]);
#pragma unroll
            for (int mt = 0; mt < 4; mt++)
                ldsm4(af[mt], As1 + (wm + mt * 16 + ar) * LDS_ROW + ac);
#pragma unroll
            for (int mt = 0; mt < 4; mt++)
#pragma unroll
                for (int nt = 0; nt < 4; nt++) mma16816(acc[mt][nt], af[mt], bf0[nt]);
        }
        __syncthreads();
    }

    const int g = lane >> 2, c2 = (lane & 3) * 2;
#pragma unroll
    for (int mt = 0; mt < 4; mt++) {
#pragma unroll
        for (int nt = 0; nt < 4; nt++) {
            int row = m0 + wm + mt * 16 + g;
            int col = n0 + wn + nt * 8 + c2;
            float v0 = alpha * acc[mt][nt][0], v1 = alpha * acc[mt][nt][1];
            float v2 = alpha * acc[mt][nt][2], v3 = alpha * acc[mt][nt][3];
            long long o0 = coff + (long long)row * ldc + col;
            long long o1 = coff + (long long)(row + 8) * ldc + col;
            if (mode != 1) {
                *(float2*)&C[o0] = make_float2(v0, v1);
                *(float2*)&C[o1] = make_float2(v2, v3);
            }
            if (mode != 0) {
                bf16 h0 = __float2bfloat16(v0), h1 = __float2bfloat16(v1);
                bf16 h2 = __float2bfloat16(v2), h3 = __float2bfloat16(v3);
                bf16 l0 = __float2bfloat16(v0 - __bfloat162float(h0));
                bf16 l1 = __float2bfloat16(v1 - __bfloat162float(h1));
                bf16 l2 = __float2bfloat16(v2 - __bfloat162float(h2));
                bf16 l3 = __float2bfloat16(v3 - __bfloat162float(h3));
                *(__nv_bfloat162*)(C0 + o0) = __nv_bfloat162(h0, h1);
                *(__nv_bfloat162*)(C0 + o1) = __nv_bfloat162(h2, h3);
                *(__nv_bfloat162*)(C1 + o0) = __nv_bfloat162(l0, l1);
                *(__nv_bfloat162*)(C1 + o1) = __nv_bfloat162(l2, l3);
            }
        }
    }
}

// ---------------- A: c[b][s][j] = sum_n Bmat[b][n][j] * w_s[n] ----------------
__global__ __launch_bounds__(256)
void cvec_kernel(const float* __restrict__ Bf,
                 const float* __restrict__ w_mu,
                 const float* __restrict__ w_sigma,
                 float* __restrict__ C)
{
    __shared__ float wm[NB], ws[NB];
    int tid = threadIdx.x, b = blockIdx.x;
    if (tid < NB) { wm[tid] = w_mu[tid]; ws[tid] = w_sigma[tid]; }
    __syncthreads();
    const float* Bb = Bf + (long long)b * NB * DM;
    float am[3] = {0.f, 0.f, 0.f}, as[3] = {0.f, 0.f, 0.f};
    for (int n = 0; n < NB; n++) {
        float u = wm[n], v = ws[n];
        const float* row = Bb + (long long)n * DM;
#pragma unroll
        for (int i = 0; i < 3; i++) {
            float x = row[tid + i * 256];
            am[i] += x * u;
            as[i] += x * v;
        }
    }
#pragma unroll
    for (int i = 0; i < 3; i++) {
        C[(long long)b * 2 * DM + tid + i * 256]      = am[i];
        C[(long long)b * 2 * DM + DM + tid + i * 256] = as[i];
    }
}

// ---------------- B: kw[bs][i] = sum_j Wk[i][j] * c[bs][j] ----------------
__global__ __launch_bounds__(256)
void kw_kernel(const float* __restrict__ Wk, const float* __restrict__ C,
               float* __restrict__ KW)
{
    __shared__ float wt[64][65];
    __shared__ float cs[16][64];
    int tid = threadIdx.x;
    int i0 = blockIdx.x * 64;
    int i = tid & 63, qg = tid >> 6;
    float acc[4] = {0.f, 0.f, 0.f, 0.f};

    for (int jc = 0; jc < DM; jc += 64) {
#pragma unroll
        for (int t = 0; t < 16; t++) {
            int idx = tid + t * 256;
            wt[idx >> 6][idx & 63] = Wk[(long long)(i0 + (idx >> 6)) * DM + jc + (idx & 63)];
        }
#pragma unroll
        for (int t = 0; t < 4; t++) {
            int idx = tid + t * 256;
            cs[idx >> 6][idx & 63] = C[(long long)(idx >> 6) * DM + jc + (idx & 63)];
        }
        __syncthreads();
#pragma unroll
        for (int jj = 0; jj < 64; jj++) {
            float w = wt[i][jj];
            acc[0] += w * cs[qg][jj];
            acc[1] += w * cs[qg + 4][jj];
            acc[2] += w * cs[qg + 8][jj];
            acc[3] += w * cs[qg + 12][jj];
        }
        __syncthreads();
    }
#pragma unroll
    for (int t = 0; t < 4; t++)
        KW[(long long)(qg + t * 4) * DM + i0 + i] = acc[t];
}

// ---------------- C: T[b][h*2+s][j] = sum_i Wq[h*64+i][j] * kw[b][s][h*64+i] ----
__global__ __launch_bounds__(128)
void tvec_kernel(const float* __restrict__ Wq, const float* __restrict__ KW,
                 float* __restrict__ T)
{
    __shared__ float kws[16][64];
    int tid = threadIdx.x;
    int h = blockIdx.y;
    int j = blockIdx.x * 128 + tid;
#pragma unroll
    for (int t = 0; t < 8; t++) {
        int idx = tid + t * 128;
        int bs = idx >> 6, ii = idx & 63;
        kws[bs][ii] = KW[(long long)bs * DM + h * 64 + ii];
    }
    __syncthreads();
    float acc[16];
#pragma unroll
    for (int v = 0; v < 16; v++) acc[v] = 0.f;
    for (int ii = 0; ii < 64; ii++) {
        float w = Wq[(long long)(h * 64 + ii) * DM + j];
#pragma unroll
        for (int v = 0; v < 16; v++) acc[v] += w * kws[v][ii];
    }
#pragma unroll
    for (int v = 0; v < 16; v++) {
        int b = v >> 1, s = v & 1;
        T[((long long)b * 24 + h * 2 + s) * DM + j] = acc[v];
    }
}

// ---------------- D: mu/ss[b,h,q] = act( q_b[q] . T[b][h*2+s] / 8 ) ----------
__global__ __launch_bounds__(256)
void musig_kernel(const float* __restrict__ qin, const float* __restrict__ T,
                  float* __restrict__ mu_out, float* __restrict__ ss_out)
{
    __shared__ float Tc[24][132];
    int tid = threadIdx.x, lane = tid & 31, warp = tid >> 5;
    int rb = blockIdx.x * 8 + warp;
    int b = rb >> 10, qrow = rb & 1023;
    const float* qr = qin + (long long)qrow * (BATCH * DM) + (long long)b * DM;
    const float* Tb = T + (long long)b * 24 * DM;

    float acc[24];
#pragma unroll
    for (int v = 0; v < 24; v++) acc[v] = 0.f;

    for (int kc = 0; kc < 6; kc++) {
        __syncthreads();
#pragma unroll
        for (int t = 0; t < 12; t++) {
            int idx = tid + t * 256;
            Tc[idx >> 7][idx & 127] = Tb[(long long)(idx >> 7) * DM + kc * 128 + (idx & 127)];
        }
        __syncthreads();
        float4 qv = *(const float4*)(qr + kc * 128 + lane * 4);
#pragma unroll
        for (int v = 0; v < 24; v++) {
            float4 tv = *(const float4*)&Tc[v][lane * 4];
            acc[v] += qv.x * tv.x + qv.y * tv.y + qv.z * tv.z + qv.w * tv.w;
        }
    }
#pragma unroll
    for (int v = 0; v < 24; v++)
#pragma unroll
        for (int o = 16; o; o >>= 1)
            acc[v] += __shfl_xor_sync(0xffffffffu, acc[v], o);

    if (lane == 0) {
#pragma unroll
        for (int v = 0; v < 24; v++) {
            int h = v >> 1;
            float d = acc[v] * 0.125f;
            long long o = ((long long)b * NH + h) * LEN + qrow;
            if ((v & 1) == 0) mu_out[o] = 1.f / (1.f + __expf(-d));
            else              ss_out[o] = (d > 20.f) ? d : log1pf(__expf(d));
        }
    }
}

// ---------------- fused r-compute + ctx = r @ V (writes split ctx) ----------------
__global__ __launch_bounds__(256)
void rv_kernel(const float* __restrict__ mu,
               const float* __restrict__ ss,
               const float* __restrict__ mu_b,
               const float* __restrict__ sigma_b,
               const float* __restrict__ V,
               bf16* __restrict__ ctx0, bf16* __restrict__ ctx1)
{
    __shared__ __align__(16) float Vs[64][68];
    __shared__ float rs[64][68];
    __shared__ float mub[NB];
    __shared__ float invs[64][2];
    __shared__ float mus[64];

    const int tid = threadIdx.x;
    const int bh = blockIdx.y;
    const int b = bh / NH, h = bh - b * NH;
    const int m0 = blockIdx.x * 64;
    const int rowbase = bh * LEN + m0;

    if (tid < NB) mub[tid] = mu_b[tid];
    if (tid < 64) mus[tid] = mu[rowbase + tid];
    if (tid < 128) {
        int row = tid >> 1, p = tid & 1;
        float sb = sigma_b[p];
        invs[row][p] = rsqrtf(sb * sb + ss[rowbase + row]);
    }
    __syncthreads();

    const int ty = tid >> 4, tx = tid & 15;
    float acc[4][4];
#pragma unroll
    for (int i = 0; i < 4; i++)
#pragma unroll
        for (int j = 0; j < 4; j++) acc[i][j] = 0.f;

    const float* Vbh = V + (long long)b * NB * DM + h * DH;
    const float C_PHI = 0.3989422804014327f;

    for (int nc = 0; nc < 4; nc++) {
        __syncthreads();
#pragma unroll
        for (int i = 0; i < 16; i++) {
            int idx = tid + i * 256;
            int k = idx >> 6, d = idx & 63;
            Vs[k][d] = Vbh[(long long)(nc * 64 + k) * DM + d];
        }
#pragma unroll
        for (int i = 0; i < 16; i++) {
            int idx = tid + i * 256;
            int n = idx & 63, m = idx >> 6;
            float iv = invs[m][n & 1];
            float t = (mus[m] - mub[nc * 64 + n]) * iv;
            rs[m][n] = C_PHI * iv * __expf(-0.5f * t * t);
        }
        __syncthreads();
#pragma unroll 16
        for (int k = 0; k < 64; k++) {
            float a0 = rs[ty * 4 + 0][k];
            float a1 = rs[ty * 4 + 1][k];
            float a2 = rs[ty * 4 + 2][k];
            float a3 = rs[ty * 4 + 3][k];
            float4 bv = *(const float4*)&Vs[k][tx * 4];
            acc[0][0] += a0 * bv.x; acc[0][1] += a0 * bv.y; acc[0][2] += a0 * bv.z; acc[0][3] += a0 * bv.w;
            acc[1][0] += a1 * bv.x; acc[1][1] += a1 * bv.y; acc[1][2] += a1 * bv.z; acc[1][3] += a1 * bv.w;
            acc[2][0] += a2 * bv.x; acc[2][1] += a2 * bv.y; acc[2][2] += a2 * bv.z; acc[2][3] += a2 * bv.w;
            acc[3][0] += a3 * bv.x; acc[3][1] += a3 * bv.y; acc[3][2] += a3 * bv.z; acc[3][3] += a3 * bv.w;
        }
    }

    long long cb = (long long)b * LEN * DM + (long long)m0 * DM + h * DH;
#pragma unroll
    for (int i = 0; i < 4; i++)
#pragma unroll
        for (int j = 0; j < 4; j++) {
            long long o = cb + (long long)(ty * 4 + i) * DM + tx * 4 + j;
            float v = acc[i][j];
            bf16 hh = __float2bfloat16(v);
            ctx0[o] = hh;
            ctx1[o] = __float2bfloat16(v - __bfloat162float(hh));
        }
}

// ---------------- launch ----------------
extern "C" void kernel_launch(void* const* d_in, const int* in_sizes, int n_in,
                              void* d_out, int out_size)
{
    const float* x       = (const float*)d_in[0];
    const float* q       = (const float*)d_in[1];
    const float* Wq      = (const float*)d_in[2];
    const float* Wk      = (const float*)d_in[3];
    const float* Wv      = (const float*)d_in[4];
    const float* Wo      = (const float*)d_in[5];
    const float* w_mu    = (const float*)d_in[6];
    const float* w_sigma = (const float*)d_in[7];
    const float* mu_b    = (const float*)d_in[8];
    const float* sigma_b = (const float*)d_in[9];
    const float* G       = (const float*)d_in[10];
    float* out = (float*)d_out;

    cudaFuncSetAttribute(mma_gemm, cudaFuncAttributeMaxDynamicSharedMemorySize, GSMEM_BYTES);

    void *pxt0, *pxt1, *pGt0, *pGt1, *pWv0, *pWv1, *pWo0, *pWo1;
    void *pB0, *pB1, *pBf, *pV, *pC, *pKW, *pT, *pMu, *pSs, *pC0, *pC1;
    cudaGetSymbolAddress(&pxt0, g_xt0); cudaGetSymbolAddress(&pxt1, g_xt1);
    cudaGetSymbolAddress(&pGt0, g_Gt0); cudaGetSymbolAddress(&pGt1, g_Gt1);
    cudaGetSymbolAddress(&pWv0, g_Wv0); cudaGetSymbolAddress(&pWv1, g_Wv1);
    cudaGetSymbolAddress(&pWo0, g_Wo0); cudaGetSymbolAddress(&pWo1, g_Wo1);
    cudaGetSymbolAddress(&pB0, g_B0);   cudaGetSymbolAddress(&pB1, g_B1);
    cudaGetSymbolAddress(&pBf, g_Bf);   cudaGetSymbolAddress(&pV, g_V);
    cudaGetSymbolAddress(&pC, g_C);     cudaGetSymbolAddress(&pKW, g_KW);
    cudaGetSymbolAddress(&pT, g_T);
    cudaGetSymbolAddress(&pMu, g_mu);   cudaGetSymbolAddress(&pSs, g_ss);
    cudaGetSymbolAddress(&pC0, g_ctx0); cudaGetSymbolAddress(&pC1, g_ctx1);

    const long long NBDM = (long long)NB * DM;
    const long long LDM  = (long long)LEN * DM;
    const long long DMLN = (long long)DM * LEN;
    dim3 blk(256);

    // ---- input conversions ----
    int nW = DM * DM;
    split_kernel<<<nW / 1024, blk>>>(Wv, (bf16*)pWv0, (bf16*)pWv1, nW);
    split_kernel<<<nW / 1024, blk>>>(Wo, (bf16*)pWo0, (bf16*)pWo1, nW);
    tsplit_kernel<<<dim3(DM / 32, LEN / 32, BATCH), dim3(32, 8)>>>(
        x, DM, BATCH * DM, (bf16*)pxt0, (bf16*)pxt1, DMLN, LEN);
    tsplit_kernel<<<dim3(NB / 32, LEN / 32, 1), dim3(32, 8)>>>(
        G, 0, NB, (bf16*)pGt0, (bf16*)pGt1, 0, LEN);

    // ---- 1. Bmat[b] = Gt (256x1024) . xt_b (768x1024)^T  (fp32 + split out) ----
    mma_gemm<<<dim3(DM / 128, NB / 128, BATCH), blk, GSMEM_BYTES>>>(
        LEN,
        (bf16*)pGt0, (bf16*)pGt1, LEN, 0, 0,
        (bf16*)pxt0, (bf16*)pxt1, LEN, DMLN, 0,
        (float*)pBf, (bf16*)pB0, (bf16*)pB1, DM, NBDM, 0,
        1, 1.0f, 2);

    // ---- 2. V[b] = Bmat_b @ Wv^T (fp32 out) ----
    mma_gemm<<<dim3(DM / 128, NB / 128, BATCH), blk, GSMEM_BYTES>>>(
        DM,
        (bf16*)pB0, (bf16*)pB1, DM, NBDM, 0,
        (bf16*)pWv0, (bf16*)pWv1, DM, 0, 0,
        (float*)pV, nullptr, nullptr, DM, NBDM, 0,
        1, 1.0f, 0);

    // ---- 3. tiny fp32 chain: c -> kw -> T -> mu/ss ----
    cvec_kernel<<<BATCH, blk>>>((const float*)pBf, w_mu, w_sigma, (float*)pC);
    kw_kernel<<<DM / 64, blk>>>(Wk, (const float*)pC, (float*)pKW);
    tvec_kernel<<<dim3(DM / 128, NH), dim3(128)>>>(Wq, (const float*)pKW, (float*)pT);
    musig_kernel<<<(BATCH * LEN) / 8, blk>>>(q, (const float*)pT,
                                             (float*)pMu, (float*)pSs);

    // ---- 4. fused r + ctx = r @ V (split ctx out) ----
    rv_kernel<<<dim3(LEN / 64, BATCH * NH), blk>>>(
        (const float*)pMu, (const float*)pSs, mu_b, sigma_b,
        (const float*)pV, (bf16*)pC0, (bf16*)pC1);

    // ---- 5. out[b] = ctx_b @ Wo^T (fp32 out) ----
    mma_gemm<<<dim3(DM / 128, LEN / 128, BATCH), blk, GSMEM_BYTES>>>(
        DM,
        (bf16*)pC0, (bf16*)pC1, DM, LDM, 0,
        (bf16*)pWo0, (bf16*)pWo1, DM, 0, 0,
        out, nullptr, nullptr, DM, LDM, 0,
        1, 1.0f, 0);
}

// round 4
// speedup vs baseline: 3.0337x; 1.0552x over previous
#include <cuda_runtime.h>
#include <cuda_bf16.h>
#include <math.h>
#include <stdint.h>

#define NH     12
#define DH     64
#define DM     768
#define NB     256
#define LEN    1024
#define BATCH  8

typedef __nv_bfloat16 bf16;

// ---------------- device scratch (static; no allocations) ----------------
__device__ __align__(16) bf16 g_xt0[BATCH * DM * LEN];   // x transposed: [b][d][l]
__device__ __align__(16) bf16 g_xt1[BATCH * DM * LEN];
__device__ __align__(16) bf16 g_Gt0[NB * LEN];           // G transposed: [n][l]
__device__ __align__(16) bf16 g_Gt1[NB * LEN];
__device__ __align__(16) bf16 g_Wv0[DM * DM]; __device__ __align__(16) bf16 g_Wv1[DM * DM];
__device__ __align__(16) bf16 g_Wo0[DM * DM]; __device__ __align__(16) bf16 g_Wo1[DM * DM];
__device__ __align__(16) bf16 g_B0 [BATCH * NB * DM];
__device__ __align__(16) bf16 g_B1 [BATCH * NB * DM];
__device__ float g_V[BATCH * NB * DM];
__device__ __align__(16) bf16 g_Vt0[BATCH * NH * DH * NB];  // V^T split: [bh][d][n]
__device__ __align__(16) bf16 g_Vt1[BATCH * NH * DH * NB];
__device__ float g_C [BATCH * 2 * DM];    // c  = Bmat^T w      [b][s][768]
__device__ float g_KW[BATCH * 2 * DM];    // kw = Wk c          [b][s][768]
__device__ float g_T [BATCH * 24 * DM];   // t  = Wq_h^T kw     [b][h*2+s][768]
__device__ float g_mu[BATCH * NH * LEN];
__device__ float g_ss[BATCH * NH * LEN];
__device__ __align__(16) bf16 g_ctx0[BATCH * LEN * DM];
__device__ __align__(16) bf16 g_ctx1[BATCH * LEN * DM];

// ---------------- split conversion: fp32 -> (hi, lo) bf16 ----------------
__global__ __launch_bounds__(256)
void split_kernel(const float* __restrict__ src, bf16* __restrict__ d0,
                  bf16* __restrict__ d1, int n)
{
    int i = (blockIdx.x * 256 + threadIdx.x) * 4;
    if (i >= n) return;
    float4 v = *(const float4*)(src + i);
    bf16 h0 = __float2bfloat16(v.x), h1 = __float2bfloat16(v.y);
    bf16 h2 = __float2bfloat16(v.z), h3 = __float2bfloat16(v.w);
    bf16 l0 = __float2bfloat16(v.x - __bfloat162float(h0));
    bf16 l1 = __float2bfloat16(v.y - __bfloat162float(h1));
    bf16 l2 = __float2bfloat16(v.z - __bfloat162float(h2));
    bf16 l3 = __float2bfloat16(v.w - __bfloat162float(h3));
    *(__nv_bfloat162*)(d0 + i)     = __nv_bfloat162(h0, h1);
    *(__nv_bfloat162*)(d0 + i + 2) = __nv_bfloat162(h2, h3);
    *(__nv_bfloat162*)(d1 + i)     = __nv_bfloat162(l0, l1);
    *(__nv_bfloat162*)(d1 + i + 2) = __nv_bfloat162(l2, l3);
}

// ---------------- transpose + split: out[n][m] = in[m][n] ----------------
__global__ __launch_bounds__(256)
void tsplit_kernel(const float* __restrict__ src, long long sb_in, int ldin,
                   bf16* __restrict__ d0, bf16* __restrict__ d1,
                   long long sb_out, int ldout)
{
    __shared__ float tile[32][33];
    int b = blockIdx.z;
    const float* s = src + (long long)b * sb_in;
    int m0 = blockIdx.y * 32, n0 = blockIdx.x * 32;
#pragma unroll
    for (int i = 0; i < 4; i++) {
        int m = m0 + threadIdx.y + i * 8;
        tile[threadIdx.y + i * 8][threadIdx.x] = s[(long long)m * ldin + n0 + threadIdx.x];
    }
    __syncthreads();
#pragma unroll
    for (int i = 0; i < 4; i++) {
        int n = n0 + threadIdx.y + i * 8;
        float v = tile[threadIdx.x][threadIdx.y + i * 8];
        long long o = (long long)b * sb_out + (long long)n * ldout + m0 + threadIdx.x;
        bf16 h = __float2bfloat16(v);
        d0[o] = h;
        d1[o] = __float2bfloat16(v - __bfloat162float(h));
    }
}

// ---------------- V transpose + split: Vt[bh][d][n] = V[b][n][h*64+d] ----------
__global__ void vtrans_kernel(const float* __restrict__ V,
                              bf16* __restrict__ Vt0, bf16* __restrict__ Vt1)
{
    __shared__ float tile[32][33];
    int bh = blockIdx.z;
    int b = bh / NH, h = bh - b * NH;
    int n0 = blockIdx.x * 32, d0 = blockIdx.y * 32;
    const float* src = V + (long long)b * NB * DM + h * DH;
#pragma unroll
    for (int i = 0; i < 4; i++) {
        int n = n0 + threadIdx.y + i * 8;
        tile[threadIdx.y + i * 8][threadIdx.x] = src[(long long)n * DM + d0 + threadIdx.x];
    }
    __syncthreads();
#pragma unroll
    for (int i = 0; i < 4; i++) {
        int d = d0 + threadIdx.y + i * 8;
        float v = tile[threadIdx.x][threadIdx.y + i * 8];
        long long o = ((long long)bh * DH + d) * NB + n0 + threadIdx.x;
        bf16 hh = __float2bfloat16(v);
        Vt0[o] = hh;
        Vt1[o] = __float2bfloat16(v - __bfloat162float(hh));
    }
}

// ---------------- mma helpers ----------------
__device__ __forceinline__ void mma16816(float* c, const uint32_t* a, const uint32_t* b)
{
    asm volatile("mma.sync.aligned.m16n8k16.row.col.f32.bf16.bf16.f32 "
                 "{%0,%1,%2,%3}, {%4,%5,%6,%7}, {%8,%9}, {%0,%1,%2,%3};"
                 : "+f"(c[0]), "+f"(c[1]), "+f"(c[2]), "+f"(c[3])
                 : "r"(a[0]), "r"(a[1]), "r"(a[2]), "r"(a[3]), "r"(b[0]), "r"(b[1]));
}
__device__ __forceinline__ void ldsm4(uint32_t* r, const bf16* p)
{
    uint32_t a = (uint32_t)__cvta_generic_to_shared(p);
    asm volatile("ldmatrix.sync.aligned.m8n8.x4.shared.b16 {%0,%1,%2,%3}, [%4];"
                 : "=r"(r[0]), "=r"(r[1]), "=r"(r[2]), "=r"(r[3]) : "r"(a));
}
__device__ __forceinline__ void ldsm2(uint32_t* r, const bf16* p)
{
    uint32_t a = (uint32_t)__cvta_generic_to_shared(p);
    asm volatile("ldmatrix.sync.aligned.m8n8.x2.shared.b16 {%0,%1}, [%2];"
                 : "=r"(r[0]), "=r"(r[1]) : "r"(a));
}
__device__ __forceinline__ void cpa16(bf16* s, const bf16* g)
{
    uint32_t sa = (uint32_t)__cvta_generic_to_shared(s);
    asm volatile("cp.async.cg.shared.global [%0], [%1], 16;" :: "r"(sa), "l"(g));
}

// ---------------- split-bf16 tensor-core GEMM ----------------
#define LDS_ROW 40
#define TSZ     (128 * LDS_ROW)
#define STAGE_H (4 * TSZ)
#define GSMEM_BYTES (2 * STAGE_H * 2)

__global__ __launch_bounds__(256)
void mma_gemm(int K,
              const bf16* __restrict__ A0, const bf16* __restrict__ A1,
              long long lda, long long sAb1, long long sAb2,
              const bf16* __restrict__ B0, const bf16* __restrict__ B1,
              long long ldb, long long sBb1, long long sBb2,
              float* __restrict__ C, bf16* __restrict__ C0, bf16* __restrict__ C1,
              long long ldc, long long sCb1, long long sCb2,
              int nz2, float alpha, int mode)
{
    extern __shared__ bf16 sm[];

    int z = blockIdx.z, z1 = z / nz2, z2 = z - z1 * nz2;
    A0 += z1 * sAb1 + z2 * sAb2;  A1 += z1 * sAb1 + z2 * sAb2;
    B0 += z1 * sBb1 + z2 * sBb2;  B1 += z1 * sBb1 + z2 * sBb2;
    const long long coff = z1 * sCb1 + z2 * sCb2;

    const int m0 = blockIdx.y * 128, n0 = blockIdx.x * 128;
    const int tid = threadIdx.x, lane = tid & 31, wid = tid >> 5;
    const int wm = (wid >> 2) * 64, wn = (wid & 3) * 32;

    float acc[4][4][4];
#pragma unroll
    for (int mt = 0; mt < 4; mt++)
#pragma unroll
        for (int nt = 0; nt < 4; nt++)
#pragma unroll
            for (int i = 0; i < 4; i++) acc[mt][nt][i] = 0.f;

    const int nstages = K >> 5;

    const int lrow = tid >> 2, lseg = tid & 3;
    auto load_stage = [&](int st, int k0) {
        bf16* base = sm + st * STAGE_H;
#pragma unroll
        for (int it = 0; it < 2; it++) {
            int row = lrow + it * 64;
            int so = row * LDS_ROW + lseg * 8;
            long long goA = (long long)(m0 + row) * lda + k0 + lseg * 8;
            long long goB = (long long)(n0 + row) * ldb + k0 + lseg * 8;
            cpa16(base + so,           A0 + goA);
            cpa16(base + TSZ + so,     A1 + goA);
            cpa16(base + 2 * TSZ + so, B0 + goB);
            cpa16(base + 3 * TSZ + so, B1 + goB);
        }
        asm volatile("cp.async.commit_group;");
    };

    load_stage(0, 0);

    for (int s = 0; s < nstages; s++) {
        if (s + 1 < nstages) {
            load_stage((s + 1) & 1, (s + 1) << 5);
            asm volatile("cp.async.wait_group 1;");
        } else {
            asm volatile("cp.async.wait_group 0;");
        }
        __syncthreads();

        const bf16* As0 = sm + (s & 1) * STAGE_H;
        const bf16* As1 = As0 + TSZ;
        const bf16* Bs0 = As0 + 2 * TSZ;
        const bf16* Bs1 = As0 + 3 * TSZ;

#pragma unroll
        for (int kk = 0; kk < 2; kk++) {
            const int ar = lane & 15, ac = kk * 16 + (lane >> 4) * 8;
            const int br = lane & 7,  bc = kk * 16 + ((lane >> 3) & 1) * 8;
            uint32_t af[4][4], bf0[4][2], bf1[4][2];
#pragma unroll
            for (int mt = 0; mt < 4; mt++)
                ldsm4(af[mt], As0 + (wm + mt * 16 + ar) * LDS_ROW + ac);
#pragma unroll
            for (int nt = 0; nt < 4; nt++) {
                ldsm2(bf0[nt], Bs0 + (wn + nt * 8 + br) * LDS_ROW + bc);
                ldsm2(bf1[nt], Bs1 + (wn + nt * 8 + br) * LDS_ROW + bc);
            }
#pragma unroll
            for (int mt = 0; mt < 4; mt++)
#pragma unroll
                for (int nt = 0; nt < 4; nt++) mma16816(acc[mt][nt], af[mt], bf0[nt]);
#pragma unroll
            for (int mt = 0; mt < 4; mt++)
#pragma unroll
                for (int nt = 0; nt < 4; nt++) mma16816(acc[mt][nt], af[mt], bf1[nt]);
#pragma unroll
            for (int mt = 0; mt < 4; mt++)
                ldsm4(af[mt], As1 + (wm + mt * 16 + ar) * LDS_ROW + ac);
#pragma unroll
            for (int mt = 0; mt < 4; mt++)
#pragma unroll
                for (int nt = 0; nt < 4; nt++) mma16816(acc[mt][nt], af[mt], bf0[nt]);
        }
        __syncthreads();
    }

    const int g = lane >> 2, c2 = (lane & 3) * 2;
#pragma unroll
    for (int mt = 0; mt < 4; mt++) {
#pragma unroll
        for (int nt = 0; nt < 4; nt++) {
            int row = m0 + wm + mt * 16 + g;
            int col = n0 + wn + nt * 8 + c2;
            float v0 = alpha * acc[mt][nt][0], v1 = alpha * acc[mt][nt][1];
            float v2 = alpha * acc[mt][nt][2], v3 = alpha * acc[mt][nt][3];
            long long o0 = coff + (long long)row * ldc + col;
            long long o1 = coff + (long long)(row + 8) * ldc + col;
            if (mode != 1) {
                *(float2*)&C[o0] = make_float2(v0, v1);
                *(float2*)&C[o1] = make_float2(v2, v3);
            }
            if (mode != 0) {
                bf16 h0 = __float2bfloat16(v0), h1 = __float2bfloat16(v1);
                bf16 h2 = __float2bfloat16(v2), h3 = __float2bfloat16(v3);
                bf16 l0 = __float2bfloat16(v0 - __bfloat162float(h0));
                bf16 l1 = __float2bfloat16(v1 - __bfloat162float(h1));
                bf16 l2 = __float2bfloat16(v2 - __bfloat162float(h2));
                bf16 l3 = __float2bfloat16(v3 - __bfloat162float(h3));
                *(__nv_bfloat162*)(C0 + o0) = __nv_bfloat162(h0, h1);
                *(__nv_bfloat162*)(C0 + o1) = __nv_bfloat162(h2, h3);
                *(__nv_bfloat162*)(C1 + o0) = __nv_bfloat162(l0, l1);
                *(__nv_bfloat162*)(C1 + o1) = __nv_bfloat162(l2, l3);
            }
        }
    }
}

// ---------------- A: c[b][s][j] = sum_n (B0+B1)[b][n][j] * w_s[n] ------------
__global__ __launch_bounds__(256)
void cvec_kernel(const bf16* __restrict__ B0, const bf16* __restrict__ B1,
                 const float* __restrict__ w_mu,
                 const float* __restrict__ w_sigma,
                 float* __restrict__ C)
{
    __shared__ float wm[NB], ws[NB];
    __shared__ float red[2][256];
    int tid = threadIdx.x;
    int b = blockIdx.y;
    int j = blockIdx.x * 128 + (tid & 127);
    int g = tid >> 7;
    if (tid < NB) { wm[tid] = w_mu[tid]; ws[tid] = w_sigma[tid]; }
    __syncthreads();

    const bf16* p0 = B0 + (long long)b * NB * DM + j;
    const bf16* p1 = B1 + (long long)b * NB * DM + j;
    float am = 0.f, as = 0.f;
    for (int n = g; n < NB; n += 2) {
        float xv = __bfloat162float(p0[(long long)n * DM]) +
                   __bfloat162float(p1[(long long)n * DM]);
        am += xv * wm[n];
        as += xv * ws[n];
    }
    red[0][tid] = am; red[1][tid] = as;
    __syncthreads();
    if (tid < 128) {
        float m2 = red[0][tid] + red[0][tid + 128];
        float s2 = red[1][tid] + red[1][tid + 128];
        C[(long long)b * 2 * DM + j]      = m2;
        C[(long long)b * 2 * DM + DM + j] = s2;
    }
}

// ---------------- B: kw[bs][i] = sum_j Wk[i][j] * c[bs][j] ----------------
__global__ __launch_bounds__(256)
void kw_kernel(const float* __restrict__ Wk, const float* __restrict__ C,
               float* __restrict__ KW)
{
    __shared__ float wt[64][65];
    __shared__ float cs[16][64];
    int tid = threadIdx.x;
    int i0 = blockIdx.x * 64;
    int i = tid & 63, qg = tid >> 6;
    float acc[4] = {0.f, 0.f, 0.f, 0.f};

    for (int jc = 0; jc < DM; jc += 64) {
#pragma unroll
        for (int t = 0; t < 16; t++) {
            int idx = tid + t * 256;
            wt[idx >> 6][idx & 63] = Wk[(long long)(i0 + (idx >> 6)) * DM + jc + (idx & 63)];
        }
#pragma unroll
        for (int t = 0; t < 4; t++) {
            int idx = tid + t * 256;
            cs[idx >> 6][idx & 63] = C[(long long)(idx >> 6) * DM + jc + (idx & 63)];
        }
        __syncthreads();
#pragma unroll
        for (int jj = 0; jj < 64; jj++) {
            float w = wt[i][jj];
            acc[0] += w * cs[qg][jj];
            acc[1] += w * cs[qg + 4][jj];
            acc[2] += w * cs[qg + 8][jj];
            acc[3] += w * cs[qg + 12][jj];
        }
        __syncthreads();
    }
#pragma unroll
    for (int t = 0; t < 4; t++)
        KW[(long long)(qg + t * 4) * DM + i0 + i] = acc[t];
}

// ---------------- C: T[b][h*2+s][j] = sum_i Wq[h*64+i][j] * kw[b][s][h*64+i] ----
__global__ __launch_bounds__(128)
void tvec_kernel(const float* __restrict__ Wq, const float* __restrict__ KW,
                 float* __restrict__ T)
{
    __shared__ float kws[16][64];
    int tid = threadIdx.x;
    int h = blockIdx.y;
    int j = blockIdx.x * 128 + tid;
#pragma unroll
    for (int t = 0; t < 8; t++) {
        int idx = tid + t * 128;
        int bs = idx >> 6, ii = idx & 63;
        kws[bs][ii] = KW[(long long)bs * DM + h * 64 + ii];
    }
    __syncthreads();
    float acc[16];
#pragma unroll
    for (int v = 0; v < 16; v++) acc[v] = 0.f;
    for (int ii = 0; ii < 64; ii++) {
        float w = Wq[(long long)(h * 64 + ii) * DM + j];
#pragma unroll
        for (int v = 0; v < 16; v++) acc[v] += w * kws[v][ii];
    }
#pragma unroll
    for (int v = 0; v < 16; v++) {
        int b = v >> 1, s = v & 1;
        T[((long long)b * 24 + h * 2 + s) * DM + j] = acc[v];
    }
}

// ---------------- D: mu/ss[b,h,q] = act( q_b[q] . T[b][h*2+s] / 8 ) ----------
__global__ __launch_bounds__(256)
void musig_kernel(const float* __restrict__ qin, const float* __restrict__ T,
                  float* __restrict__ mu_out, float* __restrict__ ss_out)
{
    __shared__ float Tc[24][132];
    int tid = threadIdx.x, lane = tid & 31, warp = tid >> 5;
    int rb = blockIdx.x * 8 + warp;
    int b = rb >> 10, qrow = rb & 1023;
    const float* qr = qin + (long long)qrow * (BATCH * DM) + (long long)b * DM;
    const float* Tb = T + (long long)b * 24 * DM;

    float acc[24];
#pragma unroll
    for (int v = 0; v < 24; v++) acc[v] = 0.f;

    for (int kc = 0; kc < 6; kc++) {
        __syncthreads();
#pragma unroll
        for (int t = 0; t < 12; t++) {
            int idx = tid + t * 256;
            Tc[idx >> 7][idx & 127] = Tb[(long long)(idx >> 7) * DM + kc * 128 + (idx & 127)];
        }
        __syncthreads();
        float4 qv = *(const float4*)(qr + kc * 128 + lane * 4);
#pragma unroll
        for (int v = 0; v < 24; v++) {
            float4 tv = *(const float4*)&Tc[v][lane * 4];
            acc[v] += qv.x * tv.x + qv.y * tv.y + qv.z * tv.z + qv.w * tv.w;
        }
    }
#pragma unroll
    for (int v = 0; v < 24; v++)
#pragma unroll
        for (int o = 16; o; o >>= 1)
            acc[v] += __shfl_xor_sync(0xffffffffu, acc[v], o);

    if (lane == 0) {
#pragma unroll
        for (int v = 0; v < 24; v++) {
            int h = v >> 1;
            float d = acc[v] * 0.125f;
            long long o = ((long long)b * NH + h) * LEN + qrow;
            if ((v & 1) == 0) mu_out[o] = 1.f / (1.f + __expf(-d));
            else              ss_out[o] = (d > 20.f) ? d : log1pf(__expf(d));
        }
    }
}

// ---------------- tensorized fused r + ctx = r @ V -------------------------
// Block: 128 q-rows x 64 d-cols for one (b,h). K = 256 basis, 8 stages of 32.
// r computed in smem (fp32 exp), split to bf16 hi/lo; 3-term mma split.
__global__ __launch_bounds__(256)
void rv_mma_kernel(const float* __restrict__ mu,
                   const float* __restrict__ ss,
                   const float* __restrict__ mu_b,
                   const float* __restrict__ sigma_b,
                   const bf16* __restrict__ Vt0, const bf16* __restrict__ Vt1,
                   bf16* __restrict__ ctx0, bf16* __restrict__ ctx1)
{
    __shared__ __align__(16) bf16 rs0[128 * LDS_ROW];
    __shared__ __align__(16) bf16 rs1[128 * LDS_ROW];
    __shared__ __align__(16) bf16 vs0[64 * LDS_ROW];
    __shared__ __align__(16) bf16 vs1[64 * LDS_ROW];
    __shared__ float mub[NB];
    __shared__ float invs[128][2];
    __shared__ float mus[128];

    const int tid = threadIdx.x, lane = tid & 31, wid = tid >> 5;
    const int bh = blockIdx.y;
    const int b = bh / NH, h = bh - b * NH;
    const int m0 = blockIdx.x * 128;
    const int rowbase = bh * LEN + m0;

    if (tid < NB) mub[tid] = mu_b[tid];
    if (tid < 128) mus[tid] = mu[rowbase + tid];
    {
        int row = tid >> 1, p = tid & 1;
        float sb = sigma_b[p];
        invs[row][p] = rsqrtf(sb * sb + ss[rowbase + row]);
    }
    __syncthreads();

    const int wm = (wid >> 1) * 32, wn = (wid & 1) * 32;
    float acc[2][4][4];
#pragma unroll
    for (int mt = 0; mt < 2; mt++)
#pragma unroll
        for (int nt = 0; nt < 4; nt++)
#pragma unroll
            for (int i = 0; i < 4; i++) acc[mt][nt][i] = 0.f;

    const bf16* vt0 = Vt0 + (long long)bh * DH * NB;
    const bf16* vt1 = Vt1 + (long long)bh * DH * NB;
    const float C_PHI = 0.3989422804014327f;

    // V tile load indices: 64 rows x 32 bf16 (64 B) per half
    const int vrow = tid >> 2, vseg = tid & 3;

    for (int nc = 0; nc < 8; nc++) {
        // async-load V chunk [64 d][32 n]
        cpa16(vs0 + vrow * LDS_ROW + vseg * 8, vt0 + (long long)vrow * NB + nc * 32 + vseg * 8);
        cpa16(vs1 + vrow * LDS_ROW + vseg * 8, vt1 + (long long)vrow * NB + nc * 32 + vseg * 8);
        asm volatile("cp.async.commit_group;");

        // compute r chunk [128 m][32 n], split
#pragma unroll
        for (int i = 0; i < 16; i++) {
            int idx = tid + i * 256;
            int m = idx >> 5, n = idx & 31;
            float iv = invs[m][n & 1];
            float t = (mus[m] - mub[nc * 32 + n]) * iv;
            float e = C_PHI * iv * __expf(-0.5f * t * t);
            bf16 hh = __float2bfloat16(e);
            rs0[m * LDS_ROW + n] = hh;
            rs1[m * LDS_ROW + n] = __float2bfloat16(e - __bfloat162float(hh));
        }
        asm volatile("cp.async.wait_group 0;");
        __syncthreads();

#pragma unroll
        for (int kk = 0; kk < 2; kk++) {
            const int ar = lane & 15, ac = kk * 16 + (lane >> 4) * 8;
            const int br = lane & 7,  bc = kk * 16 + ((lane >> 3) & 1) * 8;
            uint32_t a0[2][4], a1[2][4], b0[4][2], b1[4][2];
#pragma unroll
            for (int mt = 0; mt < 2; mt++) {
                ldsm4(a0[mt], rs0 + (wm + mt * 16 + ar) * LDS_ROW + ac);
                ldsm4(a1[mt], rs1 + (wm + mt * 16 + ar) * LDS_ROW + ac);
            }
#pragma unroll
            for (int nt = 0; nt < 4; nt++) {
                ldsm2(b0[nt], vs0 + (wn + nt * 8 + br) * LDS_ROW + bc);
                ldsm2(b1[nt], vs1 + (wn + nt * 8 + br) * LDS_ROW + bc);
            }
#pragma unroll
            for (int mt = 0; mt < 2; mt++)
#pragma unroll
                for (int nt = 0; nt < 4; nt++) {
                    mma16816(acc[mt][nt], a0[mt], b0[nt]);
                    mma16816(acc[mt][nt], a0[mt], b1[nt]);
                    mma16816(acc[mt][nt], a1[mt], b0[nt]);
                }
        }
        __syncthreads();
    }

    // epilogue: ctx[b][q][h*64+d], split bf16
    const int g = lane >> 2, c2 = (lane & 3) * 2;
#pragma unroll
    for (int mt = 0; mt < 2; mt++) {
#pragma unroll
        for (int nt = 0; nt < 4; nt++) {
            int row = m0 + wm + mt * 16 + g;
            int col = h * DH + wn + nt * 8 + c2;
            float v0 = acc[mt][nt][0], v1 = acc[mt][nt][1];
            float v2 = acc[mt][nt][2], v3 = acc[mt][nt][3];
            long long o0 = (long long)b * LEN * DM + (long long)row * DM + col;
            long long o1 = o0 + 8LL * DM;
            bf16 h0 = __float2bfloat16(v0), h1 = __float2bfloat16(v1);
            bf16 h2 = __float2bfloat16(v2), h3 = __float2bfloat16(v3);
            bf16 l0 = __float2bfloat16(v0 - __bfloat162float(h0));
            bf16 l1 = __float2bfloat16(v1 - __bfloat162float(h1));
            bf16 l2 = __float2bfloat16(v2 - __bfloat162float(h2));
            bf16 l3 = __float2bfloat16(v3 - __bfloat162float(h3));
            *(__nv_bfloat162*)(ctx0 + o0) = __nv_bfloat162(h0, h1);
            *(__nv_bfloat162*)(ctx0 + o1) = __nv_bfloat162(h2, h3);
            *(__nv_bfloat162*)(ctx1 + o0) = __nv_bfloat162(l0, l1);
            *(__nv_bfloat162*)(ctx1 + o1) = __nv_bfloat162(l2, l3);
        }
    }
}

// ---------------- launch ----------------
extern "C" void kernel_launch(void* const* d_in, const int* in_sizes, int n_in,
                              void* d_out, int out_size)
{
    const float* x       = (const float*)d_in[0];
    const float* q       = (const float*)d_in[1];
    const float* Wq      = (const float*)d_in[2];
    const float* Wk      = (const float*)d_in[3];
    const float* Wv      = (const float*)d_in[4];
    const float* Wo      = (const float*)d_in[5];
    const float* w_mu    = (const float*)d_in[6];
    const float* w_sigma = (const float*)d_in[7];
    const float* mu_b    = (const float*)d_in[8];
    const float* sigma_b = (const float*)d_in[9];
    const float* G       = (const float*)d_in[10];
    float* out = (float*)d_out;

    cudaFuncSetAttribute(mma_gemm, cudaFuncAttributeMaxDynamicSharedMemorySize, GSMEM_BYTES);

    void *pxt0, *pxt1, *pGt0, *pGt1, *pWv0, *pWv1, *pWo0, *pWo1;
    void *pB0, *pB1, *pV, *pVt0, *pVt1, *pC, *pKW, *pT, *pMu, *pSs, *pC0, *pC1;
    cudaGetSymbolAddress(&pxt0, g_xt0); cudaGetSymbolAddress(&pxt1, g_xt1);
    cudaGetSymbolAddress(&pGt0, g_Gt0); cudaGetSymbolAddress(&pGt1, g_Gt1);
    cudaGetSymbolAddress(&pWv0, g_Wv0); cudaGetSymbolAddress(&pWv1, g_Wv1);
    cudaGetSymbolAddress(&pWo0, g_Wo0); cudaGetSymbolAddress(&pWo1, g_Wo1);
    cudaGetSymbolAddress(&pB0, g_B0);   cudaGetSymbolAddress(&pB1, g_B1);
    cudaGetSymbolAddress(&pV, g_V);
    cudaGetSymbolAddress(&pVt0, g_Vt0); cudaGetSymbolAddress(&pVt1, g_Vt1);
    cudaGetSymbolAddress(&pC, g_C);     cudaGetSymbolAddress(&pKW, g_KW);
    cudaGetSymbolAddress(&pT, g_T);
    cudaGetSymbolAddress(&pMu, g_mu);   cudaGetSymbolAddress(&pSs, g_ss);
    cudaGetSymbolAddress(&pC0, g_ctx0); cudaGetSymbolAddress(&pC1, g_ctx1);

    const long long NBDM = (long long)NB * DM;
    const long long LDM  = (long long)LEN * DM;
    const long long DMLN = (long long)DM * LEN;
    dim3 blk(256);

    // ---- input conversions ----
    int nW = DM * DM;
    split_kernel<<<nW / 1024, blk>>>(Wv, (bf16*)pWv0, (bf16*)pWv1, nW);
    split_kernel<<<nW / 1024, blk>>>(Wo, (bf16*)pWo0, (bf16*)pWo1, nW);
    tsplit_kernel<<<dim3(DM / 32, LEN / 32, BATCH), dim3(32, 8)>>>(
        x, DM, BATCH * DM, (bf16*)pxt0, (bf16*)pxt1, DMLN, LEN);
    tsplit_kernel<<<dim3(NB / 32, LEN / 32, 1), dim3(32, 8)>>>(
        G, 0, NB, (bf16*)pGt0, (bf16*)pGt1, 0, LEN);

    // ---- 1. Bmat[b] = Gt . xt_b^T (split out) ----
    mma_gemm<<<dim3(DM / 128, NB / 128, BATCH), blk, GSMEM_BYTES>>>(
        LEN,
        (bf16*)pGt0, (bf16*)pGt1, LEN, 0, 0,
        (bf16*)pxt0, (bf16*)pxt1, LEN, DMLN, 0,
        nullptr, (bf16*)pB0, (bf16*)pB1, DM, NBDM, 0,
        1, 1.0f, 1);

    // ---- 2. V[b] = Bmat_b @ Wv^T (fp32 out) ----
    mma_gemm<<<dim3(DM / 128, NB / 128, BATCH), blk, GSMEM_BYTES>>>(
        DM,
        (bf16*)pB0, (bf16*)pB1, DM, NBDM, 0,
        (bf16*)pWv0, (bf16*)pWv1, DM, 0, 0,
        (float*)pV, nullptr, nullptr, DM, NBDM, 0,
        1, 1.0f, 0);

    // ---- 2b. V transpose + split: Vt[bh][d][n] ----
    vtrans_kernel<<<dim3(NB / 32, DH / 32, BATCH * NH), dim3(32, 8)>>>(
        (const float*)pV, (bf16*)pVt0, (bf16*)pVt1);

    // ---- 3. tiny fp32 chain: c -> kw -> T -> mu/ss ----
    cvec_kernel<<<dim3(DM / 128, BATCH), blk>>>(
        (const bf16*)pB0, (const bf16*)pB1, w_mu, w_sigma, (float*)pC);
    kw_kernel<<<DM / 64, blk>>>(Wk, (const float*)pC, (float*)pKW);
    tvec_kernel<<<dim3(DM / 128, NH), dim3(128)>>>(Wq, (const float*)pKW, (float*)pT);
    musig_kernel<<<(BATCH * LEN) / 8, blk>>>(q, (const float*)pT,
                                             (float*)pMu, (float*)pSs);

    // ---- 4. tensorized fused r + ctx = r @ V (split ctx out) ----
    rv_mma_kernel<<<dim3(LEN / 128, BATCH * NH), blk>>>(
        (const float*)pMu, (const float*)pSs, mu_b, sigma_b,
        (const bf16*)pVt0, (const bf16*)pVt1, (bf16*)pC0, (bf16*)pC1);

    // ---- 5. out[b] = ctx_b @ Wo^T (fp32 out) ----
    mma_gemm<<<dim3(DM / 128, LEN / 128, BATCH), blk, GSMEM_BYTES>>>(
        DM,
        (bf16*)pC0, (bf16*)pC1, DM, LDM, 0,
        (bf16*)pWo0, (bf16*)pWo1, DM, 0, 0,
        out, nullptr, nullptr, DM, LDM, 0,
        1, 1.0f, 0);
}